// round 14
// baseline (speedup 1.0000x reference)
#include <cuda_runtime.h>
#include <cuda_fp16.h>
#include <stdint.h>

#define NN 100000
#define MM 20000
#define PP 1600000
#define CIN 768
#define HID 128
#define NLAYERS 16
#define NOUT 16
#define EPSV 1e-5f

// ---------------- scratch ----------------
__device__ float  g_x[NN * HID];        // residual stream fp32
__device__ __half g_a[NN * HID];        // LN+relu'd activations fp16 (MMA input)
__device__ __half g_h[NN * HID];        // post-theta fp16
__device__ __half g_xe[MM * HID];       // edge features fp16
__device__ __half g_weT[HID * CIN];     // W_enc^T  [n][k]
__device__ __half g_wtT[NLAYERS * HID * HID]; // Wt^T per layer [n][k]
__device__ float  g_inv_ce[MM];
__device__ float  g_inv_cv[NN];
__device__ int    g_cnt_e[MM];
__device__ int    g_cnt_v[NN];
__device__ int    g_off_e[MM + 1];
__device__ int    g_off_v[NN + 1];
__device__ int    g_cur_e[MM];
__device__ int    g_cur_v[NN];
__device__ int    g_csr_ev[PP];
__device__ int    g_csr_ve[PP];
__device__ int    g_part[128];

// ---------------- degree counting ----------------
__global__ void zero_counts_kernel() {
    int i = blockIdx.x * blockDim.x + threadIdx.x;
    if (i < MM) g_cnt_e[i] = 0;
    if (i < NN) g_cnt_v[i] = 0;
}

__global__ void count_kernel(const int* __restrict__ v_idx,
                             const int* __restrict__ e_idx) {
    int i = blockIdx.x * blockDim.x + threadIdx.x;
    if (i < PP) {
        atomicAdd(&g_cnt_e[e_idx[i]], 1);
        atomicAdd(&g_cnt_v[v_idx[i]], 1);
    }
}

// ---------------- 2-level scan (+ inv folded into final pass) --------------
__global__ void scan_bsum_kernel(const int* __restrict__ cnt, int n) {
    __shared__ int wsum[8];
    int t = threadIdx.x;
    int base = blockIdx.x * 1024;
    int s = 0;
    for (int i = t; i < 1024; i += 256) {
        int idx = base + i;
        if (idx < n) s += cnt[idx];
    }
    int lane = t & 31, wid = t >> 5;
#pragma unroll
    for (int d = 16; d > 0; d >>= 1) s += __shfl_xor_sync(0xffffffffu, s, d);
    if (lane == 0) wsum[wid] = s;
    __syncthreads();
    if (t == 0) {
        int tot = 0;
#pragma unroll
        for (int i = 0; i < 8; i++) tot += wsum[i];
        g_part[blockIdx.x] = tot;
    }
}

__global__ void scan_part_kernel(int nparts) {
    __shared__ int sm[128];
    int t = threadIdx.x;
    sm[t] = (t < nparts) ? g_part[t] : 0;
    __syncthreads();
    if (t == 0) {
        int run = 0;
        for (int i = 0; i < nparts; i++) {
            int v = sm[i];
            sm[i] = run;
            run += v;
        }
    }
    __syncthreads();
    if (t < nparts) g_part[t] = sm[t];
}

__global__ void scan_final_kernel(const int* __restrict__ cnt,
                                  int* __restrict__ off,
                                  int* __restrict__ cur,
                                  float* __restrict__ inv, int n) {
    __shared__ int wpre[8];
    int t = threadIdx.x;
    int lane = t & 31, wid = t >> 5;
    int base = blockIdx.x * 1024 + t * 4;

    int local[4];
    int s = 0;
#pragma unroll
    for (int j = 0; j < 4; j++) {
        int idx = base + j;
        int v = (idx < n) ? cnt[idx] : 0;
        if (idx < n) {
            cur[idx] = 0;
            inv[idx] = 1.0f / fmaxf((float)v, 1.0f);
        }
        local[j] = v;
        s += v;
    }
    int incl = s;
#pragma unroll
    for (int d = 1; d < 32; d <<= 1) {
        int y = __shfl_up_sync(0xffffffffu, incl, d);
        if (lane >= d) incl += y;
    }
    if (lane == 31) wpre[wid] = incl;
    __syncthreads();
    if (t == 0) {
        int run = 0;
#pragma unroll
        for (int i = 0; i < 8; i++) {
            int v = wpre[i];
            wpre[i] = run;
            run += v;
        }
    }
    __syncthreads();
    int excl = incl - s + wpre[wid] + g_part[blockIdx.x];
    int run = excl;
#pragma unroll
    for (int j = 0; j < 4; j++) {
        int idx = base + j;
        run += local[j];
        if (idx < n) off[idx + 1] = run;
    }
    if (blockIdx.x == 0 && t == 0) off[0] = 0;
}

// ---------------- CSR fill --------------------------------------------------
__global__ void fill_csr_kernel(const int* __restrict__ v_idx,
                                const int* __restrict__ e_idx) {
    int i = blockIdx.x * blockDim.x + threadIdx.x;
    if (i >= PP) return;
    int v = v_idx[i];
    int e = e_idx[i];
    int pe = atomicAdd(&g_cur_e[e], 1);
    g_csr_ev[g_off_e[e] + pe] = v;
    int pv = atomicAdd(&g_cur_v[v], 1);
    g_csr_ve[g_off_v[v] + pv] = e;
}

// ---------------- weight conversion ----------------
__global__ void convert_w_kernel(const float* __restrict__ We,
                                 const float* __restrict__ Wt) {
    int i = blockIdx.x * blockDim.x + threadIdx.x;
    if (i < CIN * HID) {
        int k = i / HID, n = i % HID;
        g_weT[n * CIN + k] = __float2half(We[i]);
    }
    if (i < NLAYERS * HID * HID) {
        int l = i >> 14;
        int r = i & 16383;
        int k = r >> 7, n = r & 127;
        g_wtT[(l << 14) + n * HID + k] = __float2half(Wt[i]);
    }
}

// ---------------- mma helper ----------------
__device__ __forceinline__ void mma16816(float* c, uint32_t a0, uint32_t a1,
                                         uint32_t a2, uint32_t a3,
                                         uint32_t b0, uint32_t b1) {
    asm volatile(
        "mma.sync.aligned.m16n8k16.row.col.f32.f16.f16.f32 "
        "{%0,%1,%2,%3},{%4,%5,%6,%7},{%8,%9},{%0,%1,%2,%3};"
        : "+f"(c[0]), "+f"(c[1]), "+f"(c[2]), "+f"(c[3])
        : "r"(a0), "r"(a1), "r"(a2), "r"(a3), "r"(b0), "r"(b1));
}

__device__ __forceinline__ uint4 pack_half8(const float* f) {
    __half2 h0 = __floats2half2_rn(f[0], f[1]);
    __half2 h1 = __floats2half2_rn(f[2], f[3]);
    __half2 h2 = __floats2half2_rn(f[4], f[5]);
    __half2 h3 = __floats2half2_rn(f[6], f[7]);
    uint4 u;
    u.x = *(unsigned*)&h0; u.y = *(unsigned*)&h1;
    u.z = *(unsigned*)&h2; u.w = *(unsigned*)&h3;
    return u;
}

// ---------------- encoder GEMM (tensor core) --------------------------------
__global__ void enc_mma_kernel(const float* __restrict__ X,
                               const float* __restrict__ bias) {
    __shared__ __half As[2][64][24];
    __shared__ __half Bs[2][128][24];
    int t = threadIdx.x;
    int lane = t & 31, wid = t >> 5;
    int wr = wid >> 1, wc = wid & 1;
    int row0 = blockIdx.x * 64;

    float acc[8][4];
#pragma unroll
    for (int j = 0; j < 8; j++)
#pragma unroll
        for (int q = 0; q < 4; q++) acc[j][q] = 0.0f;

    {
        int kk = (t & 1) * 8;
        if (t < 128) {
            int row = t >> 1;
            int gr = row0 + row;
            float f[8] = {0, 0, 0, 0, 0, 0, 0, 0};
            if (gr < NN) {
                float4 v0 = *(const float4*)&X[gr * CIN + kk];
                float4 v1 = *(const float4*)&X[gr * CIN + kk + 4];
                f[0] = v0.x; f[1] = v0.y; f[2] = v0.z; f[3] = v0.w;
                f[4] = v1.x; f[5] = v1.y; f[6] = v1.z; f[7] = v1.w;
            }
            *(uint4*)&As[0][row][kk] = pack_half8(f);
        }
        int n = t >> 1;
        *(uint4*)&Bs[0][n][kk] = *(const uint4*)&g_weT[n * CIN + kk];
    }
    __syncthreads();

    for (int c = 0; c < CIN / 16; c++) {
        int cur = c & 1, nxt = cur ^ 1;
        if (c + 1 < CIN / 16) {
            int k0 = (c + 1) * 16;
            int kk = (t & 1) * 8;
            if (t < 128) {
                int row = t >> 1;
                int gr = row0 + row;
                float f[8] = {0, 0, 0, 0, 0, 0, 0, 0};
                if (gr < NN) {
                    float4 v0 = *(const float4*)&X[gr * CIN + k0 + kk];
                    float4 v1 = *(const float4*)&X[gr * CIN + k0 + kk + 4];
                    f[0] = v0.x; f[1] = v0.y; f[2] = v0.z; f[3] = v0.w;
                    f[4] = v1.x; f[5] = v1.y; f[6] = v1.z; f[7] = v1.w;
                }
                *(uint4*)&As[nxt][row][kk] = pack_half8(f);
            }
            int n = t >> 1;
            *(uint4*)&Bs[nxt][n][kk] = *(const uint4*)&g_weT[n * CIN + k0 + kk];
        }
        int ar = wr * 16 + (lane >> 2);
        int cx = (lane & 3) * 2;
        uint32_t a0 = *(uint32_t*)&As[cur][ar][cx];
        uint32_t a1 = *(uint32_t*)&As[cur][ar + 8][cx];
        uint32_t a2 = *(uint32_t*)&As[cur][ar][cx + 8];
        uint32_t a3 = *(uint32_t*)&As[cur][ar + 8][cx + 8];
#pragma unroll
        for (int j = 0; j < 8; j++) {
            int n = wc * 64 + j * 8 + (lane >> 2);
            uint32_t b0 = *(uint32_t*)&Bs[cur][n][cx];
            uint32_t b1 = *(uint32_t*)&Bs[cur][n][cx + 8];
            mma16816(acc[j], a0, a1, a2, a3, b0, b1);
        }
        __syncthreads();
    }

    int r1 = row0 + wr * 16 + (lane >> 2);
    int r2 = r1 + 8;
#pragma unroll
    for (int j = 0; j < 8; j++) {
        int cb = wc * 64 + j * 8 + (lane & 3) * 2;
        float b0 = bias[cb], b1 = bias[cb + 1];
        if (r1 < NN)
            *(float2*)&g_x[r1 * HID + cb] = make_float2(acc[j][0] + b0, acc[j][1] + b1);
        if (r2 < NN)
            *(float2*)&g_x[r2 * HID + cb] = make_float2(acc[j][2] + b0, acc[j][3] + b1);
    }
}

// ---------------- theta MMA tail (two-stage W load, 26KB smem) --------------
__device__ __forceinline__ void theta_mma_tail(
    __half (*As)[136], __half (*Ws)[72],
    const __half* __restrict__ WtT, const float* __restrict__ bb,
    int row0, int t, int lane, int wid) {
    int wr = wid >> 1, wc = wid & 1;

    float acc[8][4];
#pragma unroll
    for (int j = 0; j < 8; j++)
#pragma unroll
        for (int q = 0; q < 4; q++) acc[j][q] = 0.0f;

#pragma unroll
    for (int s = 0; s < 2; s++) {
#pragma unroll
        for (int i = 0; i < 4; i++) {
            int idx = t + i * 256;
            int n = idx >> 3, k = (idx & 7) * 8;
            *(uint4*)&Ws[n][k] = *(const uint4*)&WtT[n * HID + s * 64 + k];
        }
        __syncthreads();
#pragma unroll
        for (int c = 0; c < 4; c++) {
            int ka = s * 64 + c * 16;
            int kw = c * 16;
            int ar = wr * 16 + (lane >> 2);
            int q2 = (lane & 3) * 2;
            uint32_t a0 = *(uint32_t*)&As[ar][ka + q2];
            uint32_t a1 = *(uint32_t*)&As[ar + 8][ka + q2];
            uint32_t a2 = *(uint32_t*)&As[ar][ka + q2 + 8];
            uint32_t a3 = *(uint32_t*)&As[ar + 8][ka + q2 + 8];
#pragma unroll
            for (int j = 0; j < 8; j++) {
                int n = wc * 64 + j * 8 + (lane >> 2);
                uint32_t b0 = *(uint32_t*)&Ws[n][kw + q2];
                uint32_t b1 = *(uint32_t*)&Ws[n][kw + q2 + 8];
                mma16816(acc[j], a0, a1, a2, a3, b0, b1);
            }
        }
        __syncthreads();
    }

    int r1 = row0 + wr * 16 + (lane >> 2);
    int r2 = r1 + 8;
#pragma unroll
    for (int j = 0; j < 8; j++) {
        int cb = wc * 64 + j * 8 + (lane & 3) * 2;
        float b0 = bb[cb], b1 = bb[cb + 1];
        if (r1 < NN) {
            __half2 h = __floats2half2_rn(acc[j][0] + b0, acc[j][1] + b1);
            *(unsigned*)&g_h[r1 * HID + cb] = *(unsigned*)&h;
        }
        if (r2 < NN) {
            __half2 h = __floats2half2_rn(acc[j][2] + b0, acc[j][3] + b1);
            *(unsigned*)&g_h[r2 * HID + cb] = *(unsigned*)&h;
        }
    }
}

// ---------------- layer 0: LN(x) + theta ------------------------------------
__global__ void ln_mma_kernel(const float* __restrict__ lng,
                              const float* __restrict__ lnb,
                              const __half* __restrict__ WtT,
                              const float* __restrict__ bb) {
    __shared__ __half As[64][136];
    __shared__ __half Ws[128][72];
    int t = threadIdx.x;
    int lane = t & 31, wid = t >> 5;
    int row0 = blockIdx.x * 64;

    float4 lg = *(const float4*)&lng[lane * 4];
    float4 lb = *(const float4*)&lnb[lane * 4];
#pragma unroll
    for (int rr = 0; rr < 8; rr++) {
        int r = wid * 8 + rr;
        int row = row0 + r;
        float4 v = make_float4(0.f, 0.f, 0.f, 0.f);
        if (row < NN) v = *(const float4*)&g_x[row * HID + lane * 4];
        float s  = v.x + v.y + v.z + v.w;
        float sq = v.x * v.x + v.y * v.y + v.z * v.z + v.w * v.w;
#pragma unroll
        for (int off = 16; off > 0; off >>= 1) {
            s  += __shfl_xor_sync(0xffffffffu, s, off);
            sq += __shfl_xor_sync(0xffffffffu, sq, off);
        }
        float mu  = s * (1.0f / 128.0f);
        float var = sq * (1.0f / 128.0f) - mu * mu;
        float rs  = rsqrtf(var + EPSV);
        float h0 = fmaxf((v.x - mu) * rs * lg.x + lb.x, 0.0f);
        float h1 = fmaxf((v.y - mu) * rs * lg.y + lb.y, 0.0f);
        float h2 = fmaxf((v.z - mu) * rs * lg.z + lb.z, 0.0f);
        float h3 = fmaxf((v.w - mu) * rs * lg.w + lb.w, 0.0f);
        __half2 p01 = __floats2half2_rn(h0, h1);
        __half2 p23 = __floats2half2_rn(h2, h3);
        uint2 u;
        u.x = *(unsigned*)&p01;
        u.y = *(unsigned*)&p23;
        *(uint2*)&As[r][lane * 4] = u;
    }
    __syncthreads();
    theta_mma_tail(As, Ws, WtT, bb, row0, t, lane, wid);
}

// ---------------- layers >=1: theta on precomputed g_a ----------------------
__global__ void a_mma_kernel(const __half* __restrict__ WtT,
                             const float* __restrict__ bb) {
    __shared__ __half As[64][136];
    __shared__ __half Ws[128][72];
    int t = threadIdx.x;
    int lane = t & 31, wid = t >> 5;
    int row0 = blockIdx.x * 64;

#pragma unroll
    for (int i = 0; i < 4; i++) {
        int idx = t + i * 256;
        int row = idx >> 4;
        int cg  = idx & 15;
        int grow = row0 + row;
        uint4 u = make_uint4(0, 0, 0, 0);
        if (grow < NN) u = *(const uint4*)&g_a[grow * HID + cg * 8];
        *(uint4*)&As[row][cg * 8] = u;
    }
    __syncthreads();
    theta_mma_tail(As, Ws, WtT, bb, row0, t, lane, wid);
}

// helper: load 4 halves (8B) and add into float4 accumulator
__device__ __forceinline__ void acc_half4(float4& acc, const __half* p) {
    uint2 u = *(const uint2*)p;
    __half2 a = *(__half2*)&u.x;
    __half2 b = *(__half2*)&u.y;
    float2 fa = __half22float2(a);
    float2 fb = __half22float2(b);
    acc.x += fa.x; acc.y += fa.y; acc.z += fb.x; acc.w += fb.y;
}

// ---------------- pass 1: Xe[e] = (sum_{v in e} h[v]) * inv_ce[e] ----------
__global__ void gather_ve_kernel() {
    int w = (blockIdx.x * blockDim.x + threadIdx.x) >> 5;
    int lane = threadIdx.x & 31;
    if (w >= MM) return;
    int beg = g_off_e[w], end = g_off_e[w + 1];
    float sc = g_inv_ce[w];                 // hoisted: overlap with gather

    float4 acc = make_float4(0.f, 0.f, 0.f, 0.f);
    int j = beg;
    for (; j + 32 <= end; j += 32) {
        int vi = g_csr_ev[j + lane];
#pragma unroll
        for (int k = 0; k < 32; k += 4) {
            int v0 = __shfl_sync(0xffffffffu, vi, k);
            int v1 = __shfl_sync(0xffffffffu, vi, k + 1);
            int v2 = __shfl_sync(0xffffffffu, vi, k + 2);
            int v3 = __shfl_sync(0xffffffffu, vi, k + 3);
            acc_half4(acc, &g_h[v0 * HID + lane * 4]);
            acc_half4(acc, &g_h[v1 * HID + lane * 4]);
            acc_half4(acc, &g_h[v2 * HID + lane * 4]);
            acc_half4(acc, &g_h[v3 * HID + lane * 4]);
        }
    }
    int rem = end - j;
    if (rem > 0) {
        int vi = (lane < rem) ? g_csr_ev[j + lane] : 0;
        int k = 0;
        for (; k + 4 <= rem; k += 4) {
            int v0 = __shfl_sync(0xffffffffu, vi, k);
            int v1 = __shfl_sync(0xffffffffu, vi, k + 1);
            int v2 = __shfl_sync(0xffffffffu, vi, k + 2);
            int v3 = __shfl_sync(0xffffffffu, vi, k + 3);
            acc_half4(acc, &g_h[v0 * HID + lane * 4]);
            acc_half4(acc, &g_h[v1 * HID + lane * 4]);
            acc_half4(acc, &g_h[v2 * HID + lane * 4]);
            acc_half4(acc, &g_h[v3 * HID + lane * 4]);
        }
        for (; k < rem; k++) {
            int v = __shfl_sync(0xffffffffu, vi, k);
            acc_half4(acc, &g_h[v * HID + lane * 4]);
        }
    }
    __half2 h01 = __floats2half2_rn(acc.x * sc, acc.y * sc);
    __half2 h23 = __floats2half2_rn(acc.z * sc, acc.w * sc);
    uint2 u;
    u.x = *(unsigned*)&h01;
    u.y = *(unsigned*)&h23;
    *(uint2*)&g_xe[w * HID + lane * 4] = u;
}

// ---------------- gather_ev core (gather + residual update) ----------------
__device__ __forceinline__ float4 ev_gather_update(int w, int lane) {
    int beg = g_off_v[w], end = g_off_v[w + 1];
    float s = g_inv_cv[w];                            // hoisted
    float4 x = *(const float4*)&g_x[w * HID + lane * 4];  // hoisted: overlap latency

    float4 acc = make_float4(0.f, 0.f, 0.f, 0.f);
    int j = beg;
    for (; j + 32 <= end; j += 32) {
        int ei = g_csr_ve[j + lane];
#pragma unroll
        for (int k = 0; k < 32; k += 4) {
            int e0 = __shfl_sync(0xffffffffu, ei, k);
            int e1 = __shfl_sync(0xffffffffu, ei, k + 1);
            int e2 = __shfl_sync(0xffffffffu, ei, k + 2);
            int e3 = __shfl_sync(0xffffffffu, ei, k + 3);
            acc_half4(acc, &g_xe[e0 * HID + lane * 4]);
            acc_half4(acc, &g_xe[e1 * HID + lane * 4]);
            acc_half4(acc, &g_xe[e2 * HID + lane * 4]);
            acc_half4(acc, &g_xe[e3 * HID + lane * 4]);
        }
    }
    int rem = end - j;
    if (rem > 0) {
        int ei = (lane < rem) ? g_csr_ve[j + lane] : 0;
        int k = 0;
        for (; k + 4 <= rem; k += 4) {
            int e0 = __shfl_sync(0xffffffffu, ei, k);
            int e1 = __shfl_sync(0xffffffffu, ei, k + 1);
            int e2 = __shfl_sync(0xffffffffu, ei, k + 2);
            int e3 = __shfl_sync(0xffffffffu, ei, k + 3);
            acc_half4(acc, &g_xe[e0 * HID + lane * 4]);
            acc_half4(acc, &g_xe[e1 * HID + lane * 4]);
            acc_half4(acc, &g_xe[e2 * HID + lane * 4]);
            acc_half4(acc, &g_xe[e3 * HID + lane * 4]);
        }
        for (; k < rem; k++) {
            int e = __shfl_sync(0xffffffffu, ei, k);
            acc_half4(acc, &g_xe[e * HID + lane * 4]);
        }
    }
    x.x += fmaxf(acc.x * s, 0.0f);
    x.y += fmaxf(acc.y * s, 0.0f);
    x.z += fmaxf(acc.z * s, 0.0f);
    x.w += fmaxf(acc.w * s, 0.0f);
    *(float4*)&g_x[w * HID + lane * 4] = x;
    return x;
}

// ---------------- fused gather_ev + LN(next layer) -> g_a ------------------
__global__ void gather_ev_ln_kernel(const float* __restrict__ lng,
                                    const float* __restrict__ lnb) {
    int w = (blockIdx.x * blockDim.x + threadIdx.x) >> 5;
    int lane = threadIdx.x & 31;
    if (w >= NN) return;
    float4 xn = ev_gather_update(w, lane);

    float su = xn.x + xn.y + xn.z + xn.w;
    float sq = xn.x * xn.x + xn.y * xn.y + xn.z * xn.z + xn.w * xn.w;
#pragma unroll
    for (int off = 16; off > 0; off >>= 1) {
        su += __shfl_xor_sync(0xffffffffu, su, off);
        sq += __shfl_xor_sync(0xffffffffu, sq, off);
    }
    float mu  = su * (1.0f / 128.0f);
    float var = sq * (1.0f / 128.0f) - mu * mu;
    float rs  = rsqrtf(var + EPSV);
    float4 lg = *(const float4*)&lng[lane * 4];
    float4 lb = *(const float4*)&lnb[lane * 4];
    float h0 = fmaxf((xn.x - mu) * rs * lg.x + lb.x, 0.0f);
    float h1 = fmaxf((xn.y - mu) * rs * lg.y + lb.y, 0.0f);
    float h2 = fmaxf((xn.z - mu) * rs * lg.z + lb.z, 0.0f);
    float h3 = fmaxf((xn.w - mu) * rs * lg.w + lb.w, 0.0f);
    __half2 p01 = __floats2half2_rn(h0, h1);
    __half2 p23 = __floats2half2_rn(h2, h3);
    uint2 u;
    u.x = *(unsigned*)&p01;
    u.y = *(unsigned*)&p23;
    *(uint2*)&g_a[w * HID + lane * 4] = u;
}

// ---------------- plain gather_ev (last layer) ------------------------------
__global__ void gather_ev_kernel() {
    int w = (blockIdx.x * blockDim.x + threadIdx.x) >> 5;
    int lane = threadIdx.x & 31;
    if (w >= NN) return;
    ev_gather_update(w, lane);
}

// ---------------- head: log_softmax(x @ W_out + b_out) ---------------------
__global__ void out_kernel(const float* __restrict__ Wo,
                           const float* __restrict__ bo,
                           float* __restrict__ out) {
    __shared__ float WsT[NOUT][HID];
    __shared__ float bs[NOUT];
    int t = threadIdx.x;
    for (int i = t; i < HID * NOUT; i += 256) {
        int k = i >> 4, o = i & 15;
        WsT[o][k] = Wo[i];
    }
    if (t < NOUT) bs[t] = bo[t];
    __syncthreads();

    int w = (blockIdx.x * 256 + t) >> 5;
    int lane = t & 31;
    if (w >= NN) return;
    float4 x = *(const float4*)&g_x[w * HID + lane * 4];

    float r[NOUT];
#pragma unroll
    for (int o = 0; o < NOUT; o++) {
        float4 wv = *(const float4*)&WsT[o][lane * 4];
        float p = x.x * wv.x + x.y * wv.y + x.z * wv.z + x.w * wv.w;
#pragma unroll
        for (int off = 16; off > 0; off >>= 1)
            p += __shfl_xor_sync(0xffffffffu, p, off);
        r[o] = p + bs[o];
    }

    float m = r[0];
#pragma unroll
    for (int o = 1; o < NOUT; o++) m = fmaxf(m, r[o]);
    float sum = 0.0f;
#pragma unroll
    for (int o = 0; o < NOUT; o++) sum += expf(r[o] - m);
    float lse = m + logf(sum);

    if (lane == 0) {
#pragma unroll
        for (int o = 0; o < NOUT; o++)
            out[w * NOUT + o] = r[o] - lse;
    }
}

// ---------------- launcher ----------------
extern "C" void kernel_launch(void* const* d_in, const int* in_sizes, int n_in,
                              void* d_out, int out_size) {
    const float* X     = (const float*)d_in[0];
    const int*   v_idx = (const int*)  d_in[1];
    const int*   e_idx = (const int*)  d_in[2];
    const float* W_enc = (const float*)d_in[3];
    const float* b_enc = (const float*)d_in[4];
    const float* ln_g  = (const float*)d_in[5];
    const float* ln_b  = (const float*)d_in[6];
    const float* Wt    = (const float*)d_in[7];
    const float* bt    = (const float*)d_in[8];
    const float* W_out = (const float*)d_in[9];
    const float* b_out = (const float*)d_in[10];
    float* out = (float*)d_out;

    zero_counts_kernel<<<(NN + 255) / 256, 256>>>();
    count_kernel<<<(PP + 255) / 256, 256>>>(v_idx, e_idx);

    int* off_e; cudaGetSymbolAddress((void**)&off_e, g_off_e);
    int* off_v; cudaGetSymbolAddress((void**)&off_v, g_off_v);
    int* cnt_e; cudaGetSymbolAddress((void**)&cnt_e, g_cnt_e);
    int* cnt_v; cudaGetSymbolAddress((void**)&cnt_v, g_cnt_v);
    int* cur_e; cudaGetSymbolAddress((void**)&cur_e, g_cur_e);
    int* cur_v; cudaGetSymbolAddress((void**)&cur_v, g_cur_v);
    float* inv_e; cudaGetSymbolAddress((void**)&inv_e, g_inv_ce);
    float* inv_v; cudaGetSymbolAddress((void**)&inv_v, g_inv_cv);

    {
        int nb = (MM + 1023) / 1024;
        scan_bsum_kernel<<<nb, 256>>>(cnt_e, MM);
        scan_part_kernel<<<1, 128>>>(nb);
        scan_final_kernel<<<nb, 256>>>(cnt_e, off_e, cur_e, inv_e, MM);
    }
    {
        int nb = (NN + 1023) / 1024;
        scan_bsum_kernel<<<nb, 256>>>(cnt_v, NN);
        scan_part_kernel<<<1, 128>>>(nb);
        scan_final_kernel<<<nb, 256>>>(cnt_v, off_v, cur_v, inv_v, NN);
    }
    fill_csr_kernel<<<(PP + 255) / 256, 256>>>(v_idx, e_idx);

    convert_w_kernel<<<(NLAYERS * HID * HID + 255) / 256, 256>>>(W_enc, Wt);

    enc_mma_kernel<<<(NN + 63) / 64, 256>>>(X, b_enc);

    const __half* wtT;
    { void* p; cudaGetSymbolAddress(&p, g_wtT); wtT = (const __half*)p; }

    // layer 0 (LN from g_x)
    ln_mma_kernel<<<(NN + 63) / 64, 256>>>(ln_g, ln_b, wtT, bt);

    // 512-thread gather blocks (16 warps): fewer CTAs, same per-warp work
    const int ve_blocks = (MM + 15) / 16;
    const int ev_blocks = (NN + 15) / 16;

    for (int l = 0; l < NLAYERS - 1; l++) {
        gather_ve_kernel<<<ve_blocks, 512>>>();
        gather_ev_ln_kernel<<<ev_blocks, 512>>>(ln_g + (l + 1) * HID,
                                                ln_b + (l + 1) * HID);
        a_mma_kernel<<<(NN + 63) / 64, 256>>>(wtT + (l + 1) * HID * HID,
                                              bt + (l + 1) * HID);
    }
    gather_ve_kernel<<<ve_blocks, 512>>>();
    gather_ev_kernel<<<ev_blocks, 512>>>();

    out_kernel<<<NN / 8, 256>>>(W_out, b_out, out);
}

// round 15
// speedup vs baseline: 1.0486x; 1.0486x over previous
#include <cuda_runtime.h>
#include <cuda_fp16.h>
#include <stdint.h>

#define NN 100000
#define MM 20000
#define PP 1600000
#define CIN 768
#define HID 128
#define NLAYERS 16
#define NOUT 16
#define EPSV 1e-5f

// ---------------- scratch ----------------
__device__ float  g_x[NN * HID];        // residual stream fp32
__device__ __half g_a[NN * HID];        // LN+relu'd activations fp16 (MMA input)
__device__ __half g_h[NN * HID];        // post-theta fp16
__device__ __half g_xe[MM * HID];       // edge features fp16
__device__ __half g_weT[HID * CIN];     // W_enc^T  [n][k]
__device__ __half g_wtT[NLAYERS * HID * HID]; // Wt^T per layer [n][k]
__device__ float  g_inv_ce[MM];
__device__ float  g_inv_cv[NN];
__device__ int    g_cnt_e[MM];
__device__ int    g_cnt_v[NN];
__device__ int    g_off_e[MM + 1];
__device__ int    g_off_v[NN + 1];
__device__ int    g_cur_e[MM];
__device__ int    g_cur_v[NN];
__device__ int    g_csr_ev[PP];
__device__ int    g_csr_ve[PP];
__device__ int    g_part[128];

// ---------------- degree counting ----------------
__global__ void zero_counts_kernel() {
    int i = blockIdx.x * blockDim.x + threadIdx.x;
    if (i < MM) g_cnt_e[i] = 0;
    if (i < NN) g_cnt_v[i] = 0;
}

__global__ void count_kernel(const int* __restrict__ v_idx,
                             const int* __restrict__ e_idx) {
    int i = blockIdx.x * blockDim.x + threadIdx.x;
    if (i < PP) {
        atomicAdd(&g_cnt_e[e_idx[i]], 1);
        atomicAdd(&g_cnt_v[v_idx[i]], 1);
    }
}

__global__ void inv_kernel() {
    int i = blockIdx.x * blockDim.x + threadIdx.x;
    if (i < MM) g_inv_ce[i] = 1.0f / fmaxf((float)g_cnt_e[i], 1.0f);
    if (i < NN) g_inv_cv[i] = 1.0f / fmaxf((float)g_cnt_v[i], 1.0f);
}

// ---------------- 2-level scan ----------------------------------------------
__global__ void scan_bsum_kernel(const int* __restrict__ cnt, int n) {
    __shared__ int wsum[8];
    int t = threadIdx.x;
    int base = blockIdx.x * 1024;
    int s = 0;
    for (int i = t; i < 1024; i += 256) {
        int idx = base + i;
        if (idx < n) s += cnt[idx];
    }
    int lane = t & 31, wid = t >> 5;
#pragma unroll
    for (int d = 16; d > 0; d >>= 1) s += __shfl_xor_sync(0xffffffffu, s, d);
    if (lane == 0) wsum[wid] = s;
    __syncthreads();
    if (t == 0) {
        int tot = 0;
#pragma unroll
        for (int i = 0; i < 8; i++) tot += wsum[i];
        g_part[blockIdx.x] = tot;
    }
}

__global__ void scan_part_kernel(int nparts) {
    __shared__ int sm[128];
    int t = threadIdx.x;
    sm[t] = (t < nparts) ? g_part[t] : 0;
    __syncthreads();
    if (t == 0) {
        int run = 0;
        for (int i = 0; i < nparts; i++) {
            int v = sm[i];
            sm[i] = run;
            run += v;
        }
    }
    __syncthreads();
    if (t < nparts) g_part[t] = sm[t];
}

__global__ void scan_final_kernel(const int* __restrict__ cnt,
                                  int* __restrict__ off,
                                  int* __restrict__ cur, int n) {
    __shared__ int wpre[8];
    int t = threadIdx.x;
    int lane = t & 31, wid = t >> 5;
    int base = blockIdx.x * 1024 + t * 4;

    int local[4];
    int s = 0;
#pragma unroll
    for (int j = 0; j < 4; j++) {
        int idx = base + j;
        int v = (idx < n) ? cnt[idx] : 0;
        if (idx < n) cur[idx] = 0;
        local[j] = v;
        s += v;
    }
    int incl = s;
#pragma unroll
    for (int d = 1; d < 32; d <<= 1) {
        int y = __shfl_up_sync(0xffffffffu, incl, d);
        if (lane >= d) incl += y;
    }
    if (lane == 31) wpre[wid] = incl;
    __syncthreads();
    if (t == 0) {
        int run = 0;
#pragma unroll
        for (int i = 0; i < 8; i++) {
            int v = wpre[i];
            wpre[i] = run;
            run += v;
        }
    }
    __syncthreads();
    int excl = incl - s + wpre[wid] + g_part[blockIdx.x];
    int run = excl;
#pragma unroll
    for (int j = 0; j < 4; j++) {
        int idx = base + j;
        run += local[j];
        if (idx < n) off[idx + 1] = run;
    }
    if (blockIdx.x == 0 && t == 0) off[0] = 0;
}

// ---------------- CSR fill --------------------------------------------------
__global__ void fill_csr_kernel(const int* __restrict__ v_idx,
                                const int* __restrict__ e_idx) {
    int i = blockIdx.x * blockDim.x + threadIdx.x;
    if (i >= PP) return;
    int v = v_idx[i];
    int e = e_idx[i];
    int pe = atomicAdd(&g_cur_e[e], 1);
    g_csr_ev[g_off_e[e] + pe] = v;
    int pv = atomicAdd(&g_cur_v[v], 1);
    g_csr_ve[g_off_v[v] + pv] = e;
}

// ---------------- weight conversion ----------------
__global__ void convert_w_kernel(const float* __restrict__ We,
                                 const float* __restrict__ Wt) {
    int i = blockIdx.x * blockDim.x + threadIdx.x;
    if (i < CIN * HID) {
        int k = i / HID, n = i % HID;
        g_weT[n * CIN + k] = __float2half(We[i]);
    }
    if (i < NLAYERS * HID * HID) {
        int l = i >> 14;
        int r = i & 16383;
        int k = r >> 7, n = r & 127;
        g_wtT[(l << 14) + n * HID + k] = __float2half(Wt[i]);
    }
}

// ---------------- mma helper ----------------
__device__ __forceinline__ void mma16816(float* c, uint32_t a0, uint32_t a1,
                                         uint32_t a2, uint32_t a3,
                                         uint32_t b0, uint32_t b1) {
    asm volatile(
        "mma.sync.aligned.m16n8k16.row.col.f32.f16.f16.f32 "
        "{%0,%1,%2,%3},{%4,%5,%6,%7},{%8,%9},{%0,%1,%2,%3};"
        : "+f"(c[0]), "+f"(c[1]), "+f"(c[2]), "+f"(c[3])
        : "r"(a0), "r"(a1), "r"(a2), "r"(a3), "r"(b0), "r"(b1));
}

__device__ __forceinline__ uint4 pack_half8(const float* f) {
    __half2 h0 = __floats2half2_rn(f[0], f[1]);
    __half2 h1 = __floats2half2_rn(f[2], f[3]);
    __half2 h2 = __floats2half2_rn(f[4], f[5]);
    __half2 h3 = __floats2half2_rn(f[6], f[7]);
    uint4 u;
    u.x = *(unsigned*)&h0; u.y = *(unsigned*)&h1;
    u.z = *(unsigned*)&h2; u.w = *(unsigned*)&h3;
    return u;
}

// ---------------- encoder GEMM (tensor core) --------------------------------
__global__ void enc_mma_kernel(const float* __restrict__ X,
                               const float* __restrict__ bias) {
    __shared__ __half As[2][64][24];
    __shared__ __half Bs[2][128][24];
    int t = threadIdx.x;
    int lane = t & 31, wid = t >> 5;
    int wr = wid >> 1, wc = wid & 1;
    int row0 = blockIdx.x * 64;

    float acc[8][4];
#pragma unroll
    for (int j = 0; j < 8; j++)
#pragma unroll
        for (int q = 0; q < 4; q++) acc[j][q] = 0.0f;

    {
        int kk = (t & 1) * 8;
        if (t < 128) {
            int row = t >> 1;
            int gr = row0 + row;
            float f[8] = {0, 0, 0, 0, 0, 0, 0, 0};
            if (gr < NN) {
                float4 v0 = *(const float4*)&X[gr * CIN + kk];
                float4 v1 = *(const float4*)&X[gr * CIN + kk + 4];
                f[0] = v0.x; f[1] = v0.y; f[2] = v0.z; f[3] = v0.w;
                f[4] = v1.x; f[5] = v1.y; f[6] = v1.z; f[7] = v1.w;
            }
            *(uint4*)&As[0][row][kk] = pack_half8(f);
        }
        int n = t >> 1;
        *(uint4*)&Bs[0][n][kk] = *(const uint4*)&g_weT[n * CIN + kk];
    }
    __syncthreads();

    for (int c = 0; c < CIN / 16; c++) {
        int cur = c & 1, nxt = cur ^ 1;
        if (c + 1 < CIN / 16) {
            int k0 = (c + 1) * 16;
            int kk = (t & 1) * 8;
            if (t < 128) {
                int row = t >> 1;
                int gr = row0 + row;
                float f[8] = {0, 0, 0, 0, 0, 0, 0, 0};
                if (gr < NN) {
                    float4 v0 = *(const float4*)&X[gr * CIN + k0 + kk];
                    float4 v1 = *(const float4*)&X[gr * CIN + k0 + kk + 4];
                    f[0] = v0.x; f[1] = v0.y; f[2] = v0.z; f[3] = v0.w;
                    f[4] = v1.x; f[5] = v1.y; f[6] = v1.z; f[7] = v1.w;
                }
                *(uint4*)&As[nxt][row][kk] = pack_half8(f);
            }
            int n = t >> 1;
            *(uint4*)&Bs[nxt][n][kk] = *(const uint4*)&g_weT[n * CIN + k0 + kk];
        }
        int ar = wr * 16 + (lane >> 2);
        int cx = (lane & 3) * 2;
        uint32_t a0 = *(uint32_t*)&As[cur][ar][cx];
        uint32_t a1 = *(uint32_t*)&As[cur][ar + 8][cx];
        uint32_t a2 = *(uint32_t*)&As[cur][ar][cx + 8];
        uint32_t a3 = *(uint32_t*)&As[cur][ar + 8][cx + 8];
#pragma unroll
        for (int j = 0; j < 8; j++) {
            int n = wc * 64 + j * 8 + (lane >> 2);
            uint32_t b0 = *(uint32_t*)&Bs[cur][n][cx];
            uint32_t b1 = *(uint32_t*)&Bs[cur][n][cx + 8];
            mma16816(acc[j], a0, a1, a2, a3, b0, b1);
        }
        __syncthreads();
    }

    int r1 = row0 + wr * 16 + (lane >> 2);
    int r2 = r1 + 8;
#pragma unroll
    for (int j = 0; j < 8; j++) {
        int cb = wc * 64 + j * 8 + (lane & 3) * 2;
        float b0 = bias[cb], b1 = bias[cb + 1];
        if (r1 < NN)
            *(float2*)&g_x[r1 * HID + cb] = make_float2(acc[j][0] + b0, acc[j][1] + b1);
        if (r2 < NN)
            *(float2*)&g_x[r2 * HID + cb] = make_float2(acc[j][2] + b0, acc[j][3] + b1);
    }
}

// ---------------- theta MMA tail (shared) -----------------------------------
__device__ __forceinline__ void theta_mma_tail(
    __half (*As)[136], __half (*Ws)[72],
    const __half* __restrict__ WtT, const float* __restrict__ bb,
    int row0, int t, int lane, int wid) {
    int wr = wid >> 1, wc = wid & 1;

    float acc[8][4];
#pragma unroll
    for (int j = 0; j < 8; j++)
#pragma unroll
        for (int q = 0; q < 4; q++) acc[j][q] = 0.0f;

#pragma unroll
    for (int s = 0; s < 2; s++) {
#pragma unroll
        for (int i = 0; i < 4; i++) {
            int idx = t + i * 256;
            int n = idx >> 3, k = (idx & 7) * 8;
            *(uint4*)&Ws[n][k] = *(const uint4*)&WtT[n * HID + s * 64 + k];
        }
        __syncthreads();
#pragma unroll
        for (int c = 0; c < 4; c++) {
            int ka = s * 64 + c * 16;
            int kw = c * 16;
            int ar = wr * 16 + (lane >> 2);
            int q2 = (lane & 3) * 2;
            uint32_t a0 = *(uint32_t*)&As[ar][ka + q2];
            uint32_t a1 = *(uint32_t*)&As[ar + 8][ka + q2];
            uint32_t a2 = *(uint32_t*)&As[ar][ka + q2 + 8];
            uint32_t a3 = *(uint32_t*)&As[ar + 8][ka + q2 + 8];
#pragma unroll
            for (int j = 0; j < 8; j++) {
                int n = wc * 64 + j * 8 + (lane >> 2);
                uint32_t b0 = *(uint32_t*)&Ws[n][kw + q2];
                uint32_t b1 = *(uint32_t*)&Ws[n][kw + q2 + 8];
                mma16816(acc[j], a0, a1, a2, a3, b0, b1);
            }
        }
        __syncthreads();
    }

    int r1 = row0 + wr * 16 + (lane >> 2);
    int r2 = r1 + 8;
#pragma unroll
    for (int j = 0; j < 8; j++) {
        int cb = wc * 64 + j * 8 + (lane & 3) * 2;
        float b0 = bb[cb], b1 = bb[cb + 1];
        if (r1 < NN) {
            __half2 h = __floats2half2_rn(acc[j][0] + b0, acc[j][1] + b1);
            *(unsigned*)&g_h[r1 * HID + cb] = *(unsigned*)&h;
        }
        if (r2 < NN) {
            __half2 h = __floats2half2_rn(acc[j][2] + b0, acc[j][3] + b1);
            *(unsigned*)&g_h[r2 * HID + cb] = *(unsigned*)&h;
        }
    }
}

// ---------------- layer 0: LN(x) + theta (reads g_x fp32) ------------------
__global__ void ln_mma_kernel(const float* __restrict__ lng,
                              const float* __restrict__ lnb,
                              const __half* __restrict__ WtT,
                              const float* __restrict__ bb) {
    __shared__ __half As[64][136];
    __shared__ __half Ws[128][72];
    int t = threadIdx.x;
    int lane = t & 31, wid = t >> 5;
    int row0 = blockIdx.x * 64;

    float4 lg = *(const float4*)&lng[lane * 4];
    float4 lb = *(const float4*)&lnb[lane * 4];
#pragma unroll
    for (int rr = 0; rr < 8; rr++) {
        int r = wid * 8 + rr;
        int row = row0 + r;
        float4 v = make_float4(0.f, 0.f, 0.f, 0.f);
        if (row < NN) v = *(const float4*)&g_x[row * HID + lane * 4];
        float s  = v.x + v.y + v.z + v.w;
        float sq = v.x * v.x + v.y * v.y + v.z * v.z + v.w * v.w;
#pragma unroll
        for (int off = 16; off > 0; off >>= 1) {
            s  += __shfl_xor_sync(0xffffffffu, s, off);
            sq += __shfl_xor_sync(0xffffffffu, sq, off);
        }
        float mu  = s * (1.0f / 128.0f);
        float var = sq * (1.0f / 128.0f) - mu * mu;
        float rs  = rsqrtf(var + EPSV);
        float h0 = fmaxf((v.x - mu) * rs * lg.x + lb.x, 0.0f);
        float h1 = fmaxf((v.y - mu) * rs * lg.y + lb.y, 0.0f);
        float h2 = fmaxf((v.z - mu) * rs * lg.z + lb.z, 0.0f);
        float h3 = fmaxf((v.w - mu) * rs * lg.w + lb.w, 0.0f);
        __half2 p01 = __floats2half2_rn(h0, h1);
        __half2 p23 = __floats2half2_rn(h2, h3);
        uint2 u;
        u.x = *(unsigned*)&p01;
        u.y = *(unsigned*)&p23;
        *(uint2*)&As[r][lane * 4] = u;
    }
    __syncthreads();
    theta_mma_tail(As, Ws, WtT, bb, row0, t, lane, wid);
}

// ---------------- layers >=1: theta on precomputed g_a ----------------------
__global__ void a_mma_kernel(const __half* __restrict__ WtT,
                             const float* __restrict__ bb) {
    __shared__ __half As[64][136];
    __shared__ __half Ws[128][72];
    int t = threadIdx.x;
    int lane = t & 31, wid = t >> 5;
    int row0 = blockIdx.x * 64;

#pragma unroll
    for (int i = 0; i < 4; i++) {
        int idx = t + i * 256;
        int row = idx >> 4;
        int cg  = idx & 15;
        int grow = row0 + row;
        uint4 u = make_uint4(0, 0, 0, 0);
        if (grow < NN) u = *(const uint4*)&g_a[grow * HID + cg * 8];
        *(uint4*)&As[row][cg * 8] = u;
    }
    __syncthreads();
    theta_mma_tail(As, Ws, WtT, bb, row0, t, lane, wid);
}

// helper: load 4 halves (8B) and add into float4 accumulator
__device__ __forceinline__ void acc_half4(float4& acc, const __half* p) {
    uint2 u = *(const uint2*)p;
    __half2 a = *(__half2*)&u.x;
    __half2 b = *(__half2*)&u.y;
    float2 fa = __half22float2(a);
    float2 fb = __half22float2(b);
    acc.x += fa.x; acc.y += fa.y; acc.z += fb.x; acc.w += fb.y;
}

// ---------------- pass 1: Xe[e] = (sum_{v in e} h[v]) * inv_ce[e] ----------
__global__ void gather_ve_kernel() {
    int w = (blockIdx.x * blockDim.x + threadIdx.x) >> 5;
    int lane = threadIdx.x & 31;
    if (w >= MM) return;
    int beg = g_off_e[w], end = g_off_e[w + 1];

    float4 acc = make_float4(0.f, 0.f, 0.f, 0.f);
    int j = beg;
    for (; j + 32 <= end; j += 32) {
        int vi = g_csr_ev[j + lane];
#pragma unroll
        for (int k = 0; k < 32; k += 4) {
            int v0 = __shfl_sync(0xffffffffu, vi, k);
            int v1 = __shfl_sync(0xffffffffu, vi, k + 1);
            int v2 = __shfl_sync(0xffffffffu, vi, k + 2);
            int v3 = __shfl_sync(0xffffffffu, vi, k + 3);
            acc_half4(acc, &g_h[v0 * HID + lane * 4]);
            acc_half4(acc, &g_h[v1 * HID + lane * 4]);
            acc_half4(acc, &g_h[v2 * HID + lane * 4]);
            acc_half4(acc, &g_h[v3 * HID + lane * 4]);
        }
    }
    int rem = end - j;
    if (rem > 0) {
        int vi = (lane < rem) ? g_csr_ev[j + lane] : 0;
        int k = 0;
        for (; k + 4 <= rem; k += 4) {
            int v0 = __shfl_sync(0xffffffffu, vi, k);
            int v1 = __shfl_sync(0xffffffffu, vi, k + 1);
            int v2 = __shfl_sync(0xffffffffu, vi, k + 2);
            int v3 = __shfl_sync(0xffffffffu, vi, k + 3);
            acc_half4(acc, &g_h[v0 * HID + lane * 4]);
            acc_half4(acc, &g_h[v1 * HID + lane * 4]);
            acc_half4(acc, &g_h[v2 * HID + lane * 4]);
            acc_half4(acc, &g_h[v3 * HID + lane * 4]);
        }
        for (; k < rem; k++) {
            int v = __shfl_sync(0xffffffffu, vi, k);
            acc_half4(acc, &g_h[v * HID + lane * 4]);
        }
    }
    float sc = g_inv_ce[w];
    __half2 h01 = __floats2half2_rn(acc.x * sc, acc.y * sc);
    __half2 h23 = __floats2half2_rn(acc.z * sc, acc.w * sc);
    uint2 u;
    u.x = *(unsigned*)&h01;
    u.y = *(unsigned*)&h23;
    *(uint2*)&g_xe[w * HID + lane * 4] = u;
}

// ---------------- gather_ev core (gather + residual update) ----------------
__device__ __forceinline__ float4 ev_gather_update(int w, int lane) {
    int beg = g_off_v[w], end = g_off_v[w + 1];
    float4 acc = make_float4(0.f, 0.f, 0.f, 0.f);
    int j = beg;
    for (; j + 32 <= end; j += 32) {
        int ei = g_csr_ve[j + lane];
#pragma unroll
        for (int k = 0; k < 32; k += 4) {
            int e0 = __shfl_sync(0xffffffffu, ei, k);
            int e1 = __shfl_sync(0xffffffffu, ei, k + 1);
            int e2 = __shfl_sync(0xffffffffu, ei, k + 2);
            int e3 = __shfl_sync(0xffffffffu, ei, k + 3);
            acc_half4(acc, &g_xe[e0 * HID + lane * 4]);
            acc_half4(acc, &g_xe[e1 * HID + lane * 4]);
            acc_half4(acc, &g_xe[e2 * HID + lane * 4]);
            acc_half4(acc, &g_xe[e3 * HID + lane * 4]);
        }
    }
    int rem = end - j;
    if (rem > 0) {
        int ei = (lane < rem) ? g_csr_ve[j + lane] : 0;
        int k = 0;
        for (; k + 4 <= rem; k += 4) {
            int e0 = __shfl_sync(0xffffffffu, ei, k);
            int e1 = __shfl_sync(0xffffffffu, ei, k + 1);
            int e2 = __shfl_sync(0xffffffffu, ei, k + 2);
            int e3 = __shfl_sync(0xffffffffu, ei, k + 3);
            acc_half4(acc, &g_xe[e0 * HID + lane * 4]);
            acc_half4(acc, &g_xe[e1 * HID + lane * 4]);
            acc_half4(acc, &g_xe[e2 * HID + lane * 4]);
            acc_half4(acc, &g_xe[e3 * HID + lane * 4]);
        }
        for (; k < rem; k++) {
            int e = __shfl_sync(0xffffffffu, ei, k);
            acc_half4(acc, &g_xe[e * HID + lane * 4]);
        }
    }
    float s = g_inv_cv[w];
    float4 x = *(const float4*)&g_x[w * HID + lane * 4];
    x.x += fmaxf(acc.x * s, 0.0f);
    x.y += fmaxf(acc.y * s, 0.0f);
    x.z += fmaxf(acc.z * s, 0.0f);
    x.w += fmaxf(acc.w * s, 0.0f);
    *(float4*)&g_x[w * HID + lane * 4] = x;
    return x;
}

// ---------------- fused gather_ev + LN(next layer) -> g_a ------------------
__global__ void gather_ev_ln_kernel(const float* __restrict__ lng,
                                    const float* __restrict__ lnb) {
    int w = (blockIdx.x * blockDim.x + threadIdx.x) >> 5;
    int lane = threadIdx.x & 31;
    if (w >= NN) return;
    float4 xn = ev_gather_update(w, lane);

    float su = xn.x + xn.y + xn.z + xn.w;
    float sq = xn.x * xn.x + xn.y * xn.y + xn.z * xn.z + xn.w * xn.w;
#pragma unroll
    for (int off = 16; off > 0; off >>= 1) {
        su += __shfl_xor_sync(0xffffffffu, su, off);
        sq += __shfl_xor_sync(0xffffffffu, sq, off);
    }
    float mu  = su * (1.0f / 128.0f);
    float var = sq * (1.0f / 128.0f) - mu * mu;
    float rs  = rsqrtf(var + EPSV);
    float4 lg = *(const float4*)&lng[lane * 4];
    float4 lb = *(const float4*)&lnb[lane * 4];
    float h0 = fmaxf((xn.x - mu) * rs * lg.x + lb.x, 0.0f);
    float h1 = fmaxf((xn.y - mu) * rs * lg.y + lb.y, 0.0f);
    float h2 = fmaxf((xn.z - mu) * rs * lg.z + lb.z, 0.0f);
    float h3 = fmaxf((xn.w - mu) * rs * lg.w + lb.w, 0.0f);
    __half2 p01 = __floats2half2_rn(h0, h1);
    __half2 p23 = __floats2half2_rn(h2, h3);
    uint2 u;
    u.x = *(unsigned*)&p01;
    u.y = *(unsigned*)&p23;
    *(uint2*)&g_a[w * HID + lane * 4] = u;
}

// ---------------- plain gather_ev (last layer) ------------------------------
__global__ void gather_ev_kernel() {
    int w = (blockIdx.x * blockDim.x + threadIdx.x) >> 5;
    int lane = threadIdx.x & 31;
    if (w >= NN) return;
    ev_gather_update(w, lane);
}

// ---------------- head: log_softmax(x @ W_out + b_out) ---------------------
__global__ void out_kernel(const float* __restrict__ Wo,
                           const float* __restrict__ bo,
                           float* __restrict__ out) {
    __shared__ float WsT[NOUT][HID];
    __shared__ float bs[NOUT];
    int t = threadIdx.x;
    for (int i = t; i < HID * NOUT; i += 256) {
        int k = i >> 4, o = i & 15;
        WsT[o][k] = Wo[i];
    }
    if (t < NOUT) bs[t] = bo[t];
    __syncthreads();

    int w = (blockIdx.x * 256 + t) >> 5;
    int lane = t & 31;
    if (w >= NN) return;
    float4 x = *(const float4*)&g_x[w * HID + lane * 4];

    float r[NOUT];
#pragma unroll
    for (int o = 0; o < NOUT; o++) {
        float4 wv = *(const float4*)&WsT[o][lane * 4];
        float p = x.x * wv.x + x.y * wv.y + x.z * wv.z + x.w * wv.w;
#pragma unroll
        for (int off = 16; off > 0; off >>= 1)
            p += __shfl_xor_sync(0xffffffffu, p, off);
        r[o] = p + bs[o];
    }

    float m = r[0];
#pragma unroll
    for (int o = 1; o < NOUT; o++) m = fmaxf(m, r[o]);
    float sum = 0.0f;
#pragma unroll
    for (int o = 0; o < NOUT; o++) sum += expf(r[o] - m);
    float lse = m + logf(sum);

    if (lane == 0) {
#pragma unroll
        for (int o = 0; o < NOUT; o++)
            out[w * NOUT + o] = r[o] - lse;
    }
}

// ---------------- launcher ----------------
extern "C" void kernel_launch(void* const* d_in, const int* in_sizes, int n_in,
                              void* d_out, int out_size) {
    const float* X     = (const float*)d_in[0];
    const int*   v_idx = (const int*)  d_in[1];
    const int*   e_idx = (const int*)  d_in[2];
    const float* W_enc = (const float*)d_in[3];
    const float* b_enc = (const float*)d_in[4];
    const float* ln_g  = (const float*)d_in[5];
    const float* ln_b  = (const float*)d_in[6];
    const float* Wt    = (const float*)d_in[7];
    const float* bt    = (const float*)d_in[8];
    const float* W_out = (const float*)d_in[9];
    const float* b_out = (const float*)d_in[10];
    float* out = (float*)d_out;

    zero_counts_kernel<<<(NN + 255) / 256, 256>>>();
    count_kernel<<<(PP + 255) / 256, 256>>>(v_idx, e_idx);
    inv_kernel<<<(NN + 255) / 256, 256>>>();

    int* off_e; cudaGetSymbolAddress((void**)&off_e, g_off_e);
    int* off_v; cudaGetSymbolAddress((void**)&off_v, g_off_v);
    int* cnt_e; cudaGetSymbolAddress((void**)&cnt_e, g_cnt_e);
    int* cnt_v; cudaGetSymbolAddress((void**)&cnt_v, g_cnt_v);
    int* cur_e; cudaGetSymbolAddress((void**)&cur_e, g_cur_e);
    int* cur_v; cudaGetSymbolAddress((void**)&cur_v, g_cur_v);

    {
        int nb = (MM + 1023) / 1024;
        scan_bsum_kernel<<<nb, 256>>>(cnt_e, MM);
        scan_part_kernel<<<1, 128>>>(nb);
        scan_final_kernel<<<nb, 256>>>(cnt_e, off_e, cur_e, MM);
    }
    {
        int nb = (NN + 1023) / 1024;
        scan_bsum_kernel<<<nb, 256>>>(cnt_v, NN);
        scan_part_kernel<<<1, 128>>>(nb);
        scan_final_kernel<<<nb, 256>>>(cnt_v, off_v, cur_v, NN);
    }
    fill_csr_kernel<<<(PP + 255) / 256, 256>>>(v_idx, e_idx);

    convert_w_kernel<<<(NLAYERS * HID * HID + 255) / 256, 256>>>(W_enc, Wt);

    enc_mma_kernel<<<(NN + 63) / 64, 256>>>(X, b_enc);

    const __half* wtT;
    { void* p; cudaGetSymbolAddress(&p, g_wtT); wtT = (const __half*)p; }

    // layer 0 (LN from g_x)
    ln_mma_kernel<<<(NN + 63) / 64, 256>>>(ln_g, ln_b, wtT, bt);

    for (int l = 0; l < NLAYERS - 1; l++) {
        gather_ve_kernel<<<(MM + 7) / 8, 256>>>();
        gather_ev_ln_kernel<<<(NN + 7) / 8, 256>>>(ln_g + (l + 1) * HID,
                                                   ln_b + (l + 1) * HID);
        a_mma_kernel<<<(NN + 63) / 64, 256>>>(wtT + (l + 1) * HID * HID,
                                              bt + (l + 1) * HID);
    }
    gather_ve_kernel<<<(MM + 7) / 8, 256>>>();
    gather_ev_kernel<<<(NN + 7) / 8, 256>>>();

    out_kernel<<<NN / 8, 256>>>(W_out, b_out, out);
}

// round 16
// speedup vs baseline: 1.0521x; 1.0033x over previous
#include <cuda_runtime.h>
#include <cuda_fp16.h>
#include <stdint.h>

#define NN 100000
#define MM 20000
#define PP 1600000
#define CIN 768
#define HID 128
#define NLAYERS 16
#define NOUT 16
#define EPSV 1e-5f

// ---------------- scratch ----------------
__device__ float  g_x[NN * HID];        // residual stream fp32
__device__ __half g_a[NN * HID];        // LN+relu'd activations fp16 (MMA input)
__device__ __half g_h[NN * HID];        // post-theta fp16
__device__ __half g_xe[MM * HID];       // edge features fp16
__device__ __half g_weT[HID * CIN];     // W_enc^T  [n][k]
__device__ __half g_wtT[NLAYERS * HID * HID]; // Wt^T per layer [n][k]
__device__ float  g_inv_ce[MM];
__device__ float  g_inv_cv[NN];
__device__ int    g_cnt_e[MM];
__device__ int    g_cnt_v[NN];
__device__ int    g_off_e[MM + 1];
__device__ int    g_off_v[NN + 1];
__device__ int    g_cur_e[MM];
__device__ int    g_cur_v[NN];
__device__ int    g_csr_ev[PP];
__device__ int    g_csr_ve[PP];
__device__ int    g_part[128];

// ---------------- degree counting ----------------
__global__ void count_kernel(const int* __restrict__ v_idx,
                             const int* __restrict__ e_idx) {
    int i = blockIdx.x * blockDim.x + threadIdx.x;
    if (i < PP) {
        atomicAdd(&g_cnt_e[e_idx[i]], 1);
        atomicAdd(&g_cnt_v[v_idx[i]], 1);
    }
}

__global__ void inv_kernel() {
    int i = blockIdx.x * blockDim.x + threadIdx.x;
    if (i < MM) g_inv_ce[i] = 1.0f / fmaxf((float)g_cnt_e[i], 1.0f);
    if (i < NN) g_inv_cv[i] = 1.0f / fmaxf((float)g_cnt_v[i], 1.0f);
}

// ---------------- 2-level scan ----------------------------------------------
__global__ void scan_bsum_kernel(const int* __restrict__ cnt, int n) {
    __shared__ int wsum[8];
    int t = threadIdx.x;
    int base = blockIdx.x * 1024;
    int s = 0;
    for (int i = t; i < 1024; i += 256) {
        int idx = base + i;
        if (idx < n) s += cnt[idx];
    }
    int lane = t & 31, wid = t >> 5;
#pragma unroll
    for (int d = 16; d > 0; d >>= 1) s += __shfl_xor_sync(0xffffffffu, s, d);
    if (lane == 0) wsum[wid] = s;
    __syncthreads();
    if (t == 0) {
        int tot = 0;
#pragma unroll
        for (int i = 0; i < 8; i++) tot += wsum[i];
        g_part[blockIdx.x] = tot;
    }
}

__global__ void scan_part_kernel(int nparts) {
    __shared__ int sm[128];
    int t = threadIdx.x;
    sm[t] = (t < nparts) ? g_part[t] : 0;
    __syncthreads();
    if (t == 0) {
        int run = 0;
        for (int i = 0; i < nparts; i++) {
            int v = sm[i];
            sm[i] = run;
            run += v;
        }
    }
    __syncthreads();
    if (t < nparts) g_part[t] = sm[t];
}

__global__ void scan_final_kernel(const int* __restrict__ cnt,
                                  int* __restrict__ off,
                                  int* __restrict__ cur, int n) {
    __shared__ int wpre[8];
    int t = threadIdx.x;
    int lane = t & 31, wid = t >> 5;
    int base = blockIdx.x * 1024 + t * 4;

    int local[4];
    int s = 0;
#pragma unroll
    for (int j = 0; j < 4; j++) {
        int idx = base + j;
        int v = (idx < n) ? cnt[idx] : 0;
        if (idx < n) cur[idx] = 0;
        local[j] = v;
        s += v;
    }
    int incl = s;
#pragma unroll
    for (int d = 1; d < 32; d <<= 1) {
        int y = __shfl_up_sync(0xffffffffu, incl, d);
        if (lane >= d) incl += y;
    }
    if (lane == 31) wpre[wid] = incl;
    __syncthreads();
    if (t == 0) {
        int run = 0;
#pragma unroll
        for (int i = 0; i < 8; i++) {
            int v = wpre[i];
            wpre[i] = run;
            run += v;
        }
    }
    __syncthreads();
    int excl = incl - s + wpre[wid] + g_part[blockIdx.x];
    int run = excl;
#pragma unroll
    for (int j = 0; j < 4; j++) {
        int idx = base + j;
        run += local[j];
        if (idx < n) off[idx + 1] = run;
    }
    if (blockIdx.x == 0 && t == 0) off[0] = 0;
}

// ---------------- CSR fill --------------------------------------------------
__global__ void fill_csr_kernel(const int* __restrict__ v_idx,
                                const int* __restrict__ e_idx) {
    int i = blockIdx.x * blockDim.x + threadIdx.x;
    if (i >= PP) return;
    int v = v_idx[i];
    int e = e_idx[i];
    int pe = atomicAdd(&g_cur_e[e], 1);
    g_csr_ev[g_off_e[e] + pe] = v;
    int pv = atomicAdd(&g_cur_v[v], 1);
    g_csr_ve[g_off_v[v] + pv] = e;
}

// ---------------- weight conversion ----------------
__global__ void convert_w_kernel(const float* __restrict__ We,
                                 const float* __restrict__ Wt) {
    int i = blockIdx.x * blockDim.x + threadIdx.x;
    if (i < CIN * HID) {
        int k = i / HID, n = i % HID;
        g_weT[n * CIN + k] = __float2half(We[i]);
    }
    if (i < NLAYERS * HID * HID) {
        int l = i >> 14;
        int r = i & 16383;
        int k = r >> 7, n = r & 127;
        g_wtT[(l << 14) + n * HID + k] = __float2half(Wt[i]);
    }
}

// ---------------- mma helper ----------------
__device__ __forceinline__ void mma16816(float* c, uint32_t a0, uint32_t a1,
                                         uint32_t a2, uint32_t a3,
                                         uint32_t b0, uint32_t b1) {
    asm volatile(
        "mma.sync.aligned.m16n8k16.row.col.f32.f16.f16.f32 "
        "{%0,%1,%2,%3},{%4,%5,%6,%7},{%8,%9},{%0,%1,%2,%3};"
        : "+f"(c[0]), "+f"(c[1]), "+f"(c[2]), "+f"(c[3])
        : "r"(a0), "r"(a1), "r"(a2), "r"(a3), "r"(b0), "r"(b1));
}

__device__ __forceinline__ uint4 pack_half8(const float* f) {
    __half2 h0 = __floats2half2_rn(f[0], f[1]);
    __half2 h1 = __floats2half2_rn(f[2], f[3]);
    __half2 h2 = __floats2half2_rn(f[4], f[5]);
    __half2 h3 = __floats2half2_rn(f[6], f[7]);
    uint4 u;
    u.x = *(unsigned*)&h0; u.y = *(unsigned*)&h1;
    u.z = *(unsigned*)&h2; u.w = *(unsigned*)&h3;
    return u;
}

// ---------------- encoder GEMM (tensor core) --------------------------------
__global__ void enc_mma_kernel(const float* __restrict__ X,
                               const float* __restrict__ bias) {
    __shared__ __half As[2][64][24];
    __shared__ __half Bs[2][128][24];
    int t = threadIdx.x;
    int lane = t & 31, wid = t >> 5;
    int wr = wid >> 1, wc = wid & 1;
    int row0 = blockIdx.x * 64;

    float acc[8][4];
#pragma unroll
    for (int j = 0; j < 8; j++)
#pragma unroll
        for (int q = 0; q < 4; q++) acc[j][q] = 0.0f;

    {
        int kk = (t & 1) * 8;
        if (t < 128) {
            int row = t >> 1;
            int gr = row0 + row;
            float f[8] = {0, 0, 0, 0, 0, 0, 0, 0};
            if (gr < NN) {
                float4 v0 = *(const float4*)&X[gr * CIN + kk];
                float4 v1 = *(const float4*)&X[gr * CIN + kk + 4];
                f[0] = v0.x; f[1] = v0.y; f[2] = v0.z; f[3] = v0.w;
                f[4] = v1.x; f[5] = v1.y; f[6] = v1.z; f[7] = v1.w;
            }
            *(uint4*)&As[0][row][kk] = pack_half8(f);
        }
        int n = t >> 1;
        *(uint4*)&Bs[0][n][kk] = *(const uint4*)&g_weT[n * CIN + kk];
    }
    __syncthreads();

    for (int c = 0; c < CIN / 16; c++) {
        int cur = c & 1, nxt = cur ^ 1;
        if (c + 1 < CIN / 16) {
            int k0 = (c + 1) * 16;
            int kk = (t & 1) * 8;
            if (t < 128) {
                int row = t >> 1;
                int gr = row0 + row;
                float f[8] = {0, 0, 0, 0, 0, 0, 0, 0};
                if (gr < NN) {
                    float4 v0 = *(const float4*)&X[gr * CIN + k0 + kk];
                    float4 v1 = *(const float4*)&X[gr * CIN + k0 + kk + 4];
                    f[0] = v0.x; f[1] = v0.y; f[2] = v0.z; f[3] = v0.w;
                    f[4] = v1.x; f[5] = v1.y; f[6] = v1.z; f[7] = v1.w;
                }
                *(uint4*)&As[nxt][row][kk] = pack_half8(f);
            }
            int n = t >> 1;
            *(uint4*)&Bs[nxt][n][kk] = *(const uint4*)&g_weT[n * CIN + k0 + kk];
        }
        int ar = wr * 16 + (lane >> 2);
        int cx = (lane & 3) * 2;
        uint32_t a0 = *(uint32_t*)&As[cur][ar][cx];
        uint32_t a1 = *(uint32_t*)&As[cur][ar + 8][cx];
        uint32_t a2 = *(uint32_t*)&As[cur][ar][cx + 8];
        uint32_t a3 = *(uint32_t*)&As[cur][ar + 8][cx + 8];
#pragma unroll
        for (int j = 0; j < 8; j++) {
            int n = wc * 64 + j * 8 + (lane >> 2);
            uint32_t b0 = *(uint32_t*)&Bs[cur][n][cx];
            uint32_t b1 = *(uint32_t*)&Bs[cur][n][cx + 8];
            mma16816(acc[j], a0, a1, a2, a3, b0, b1);
        }
        __syncthreads();
    }

    int r1 = row0 + wr * 16 + (lane >> 2);
    int r2 = r1 + 8;
#pragma unroll
    for (int j = 0; j < 8; j++) {
        int cb = wc * 64 + j * 8 + (lane & 3) * 2;
        float b0 = bias[cb], b1 = bias[cb + 1];
        if (r1 < NN)
            *(float2*)&g_x[r1 * HID + cb] = make_float2(acc[j][0] + b0, acc[j][1] + b1);
        if (r2 < NN)
            *(float2*)&g_x[r2 * HID + cb] = make_float2(acc[j][2] + b0, acc[j][3] + b1);
    }
}

// ---------------- theta MMA tail (shared) -----------------------------------
__device__ __forceinline__ void theta_mma_tail(
    __half (*As)[136], __half (*Ws)[72],
    const __half* __restrict__ WtT, const float* __restrict__ bb,
    int row0, int t, int lane, int wid) {
    int wr = wid >> 1, wc = wid & 1;

    float acc[8][4];
#pragma unroll
    for (int j = 0; j < 8; j++)
#pragma unroll
        for (int q = 0; q < 4; q++) acc[j][q] = 0.0f;

#pragma unroll
    for (int s = 0; s < 2; s++) {
#pragma unroll
        for (int i = 0; i < 4; i++) {
            int idx = t + i * 256;
            int n = idx >> 3, k = (idx & 7) * 8;
            *(uint4*)&Ws[n][k] = *(const uint4*)&WtT[n * HID + s * 64 + k];
        }
        __syncthreads();
#pragma unroll
        for (int c = 0; c < 4; c++) {
            int ka = s * 64 + c * 16;
            int kw = c * 16;
            int ar = wr * 16 + (lane >> 2);
            int q2 = (lane & 3) * 2;
            uint32_t a0 = *(uint32_t*)&As[ar][ka + q2];
            uint32_t a1 = *(uint32_t*)&As[ar + 8][ka + q2];
            uint32_t a2 = *(uint32_t*)&As[ar][ka + q2 + 8];
            uint32_t a3 = *(uint32_t*)&As[ar + 8][ka + q2 + 8];
#pragma unroll
            for (int j = 0; j < 8; j++) {
                int n = wc * 64 + j * 8 + (lane >> 2);
                uint32_t b0 = *(uint32_t*)&Ws[n][kw + q2];
                uint32_t b1 = *(uint32_t*)&Ws[n][kw + q2 + 8];
                mma16816(acc[j], a0, a1, a2, a3, b0, b1);
            }
        }
        __syncthreads();
    }

    int r1 = row0 + wr * 16 + (lane >> 2);
    int r2 = r1 + 8;
#pragma unroll
    for (int j = 0; j < 8; j++) {
        int cb = wc * 64 + j * 8 + (lane & 3) * 2;
        float b0 = bb[cb], b1 = bb[cb + 1];
        if (r1 < NN) {
            __half2 h = __floats2half2_rn(acc[j][0] + b0, acc[j][1] + b1);
            *(unsigned*)&g_h[r1 * HID + cb] = *(unsigned*)&h;
        }
        if (r2 < NN) {
            __half2 h = __floats2half2_rn(acc[j][2] + b0, acc[j][3] + b1);
            *(unsigned*)&g_h[r2 * HID + cb] = *(unsigned*)&h;
        }
    }
}

// ---------------- layer 0: LN(x) + theta (reads g_x fp32) ------------------
__global__ void ln_mma_kernel(const float* __restrict__ lng,
                              const float* __restrict__ lnb,
                              const __half* __restrict__ WtT,
                              const float* __restrict__ bb) {
    __shared__ __half As[64][136];
    __shared__ __half Ws[128][72];
    int t = threadIdx.x;
    int lane = t & 31, wid = t >> 5;
    int row0 = blockIdx.x * 64;

    float4 lg = *(const float4*)&lng[lane * 4];
    float4 lb = *(const float4*)&lnb[lane * 4];
#pragma unroll
    for (int rr = 0; rr < 8; rr++) {
        int r = wid * 8 + rr;
        int row = row0 + r;
        float4 v = make_float4(0.f, 0.f, 0.f, 0.f);
        if (row < NN) v = *(const float4*)&g_x[row * HID + lane * 4];
        float s  = v.x + v.y + v.z + v.w;
        float sq = v.x * v.x + v.y * v.y + v.z * v.z + v.w * v.w;
#pragma unroll
        for (int off = 16; off > 0; off >>= 1) {
            s  += __shfl_xor_sync(0xffffffffu, s, off);
            sq += __shfl_xor_sync(0xffffffffu, sq, off);
        }
        float mu  = s * (1.0f / 128.0f);
        float var = sq * (1.0f / 128.0f) - mu * mu;
        float rs  = rsqrtf(var + EPSV);
        float h0 = fmaxf((v.x - mu) * rs * lg.x + lb.x, 0.0f);
        float h1 = fmaxf((v.y - mu) * rs * lg.y + lb.y, 0.0f);
        float h2 = fmaxf((v.z - mu) * rs * lg.z + lb.z, 0.0f);
        float h3 = fmaxf((v.w - mu) * rs * lg.w + lb.w, 0.0f);
        __half2 p01 = __floats2half2_rn(h0, h1);
        __half2 p23 = __floats2half2_rn(h2, h3);
        uint2 u;
        u.x = *(unsigned*)&p01;
        u.y = *(unsigned*)&p23;
        *(uint2*)&As[r][lane * 4] = u;
    }
    __syncthreads();
    theta_mma_tail(As, Ws, WtT, bb, row0, t, lane, wid);
}

// ---------------- layers >=1: theta on precomputed g_a ----------------------
__global__ void a_mma_kernel(const __half* __restrict__ WtT,
                             const float* __restrict__ bb) {
    __shared__ __half As[64][136];
    __shared__ __half Ws[128][72];
    int t = threadIdx.x;
    int lane = t & 31, wid = t >> 5;
    int row0 = blockIdx.x * 64;

#pragma unroll
    for (int i = 0; i < 4; i++) {
        int idx = t + i * 256;
        int row = idx >> 4;
        int cg  = idx & 15;
        int grow = row0 + row;
        uint4 u = make_uint4(0, 0, 0, 0);
        if (grow < NN) u = *(const uint4*)&g_a[grow * HID + cg * 8];
        *(uint4*)&As[row][cg * 8] = u;
    }
    __syncthreads();
    theta_mma_tail(As, Ws, WtT, bb, row0, t, lane, wid);
}

// helper: load 4 halves (8B) and add into float4 accumulator
__device__ __forceinline__ void acc_half4(float4& acc, const __half* p) {
    uint2 u = *(const uint2*)p;
    __half2 a = *(__half2*)&u.x;
    __half2 b = *(__half2*)&u.y;
    float2 fa = __half22float2(a);
    float2 fb = __half22float2(b);
    acc.x += fa.x; acc.y += fa.y; acc.z += fb.x; acc.w += fb.y;
}

// ---------------- pass 1: Xe[e] = (sum_{v in e} h[v]) * inv_ce[e] ----------
__global__ void gather_ve_kernel() {
    int w = (blockIdx.x * blockDim.x + threadIdx.x) >> 5;
    int lane = threadIdx.x & 31;
    if (w >= MM) return;
    int beg = g_off_e[w], end = g_off_e[w + 1];

    float4 acc = make_float4(0.f, 0.f, 0.f, 0.f);
    int j = beg;
    for (; j + 32 <= end; j += 32) {
        int vi = g_csr_ev[j + lane];
#pragma unroll
        for (int k = 0; k < 32; k += 4) {
            int v0 = __shfl_sync(0xffffffffu, vi, k);
            int v1 = __shfl_sync(0xffffffffu, vi, k + 1);
            int v2 = __shfl_sync(0xffffffffu, vi, k + 2);
            int v3 = __shfl_sync(0xffffffffu, vi, k + 3);
            acc_half4(acc, &g_h[v0 * HID + lane * 4]);
            acc_half4(acc, &g_h[v1 * HID + lane * 4]);
            acc_half4(acc, &g_h[v2 * HID + lane * 4]);
            acc_half4(acc, &g_h[v3 * HID + lane * 4]);
        }
    }
    int rem = end - j;
    if (rem > 0) {
        int vi = (lane < rem) ? g_csr_ev[j + lane] : 0;
        int k = 0;
        for (; k + 4 <= rem; k += 4) {
            int v0 = __shfl_sync(0xffffffffu, vi, k);
            int v1 = __shfl_sync(0xffffffffu, vi, k + 1);
            int v2 = __shfl_sync(0xffffffffu, vi, k + 2);
            int v3 = __shfl_sync(0xffffffffu, vi, k + 3);
            acc_half4(acc, &g_h[v0 * HID + lane * 4]);
            acc_half4(acc, &g_h[v1 * HID + lane * 4]);
            acc_half4(acc, &g_h[v2 * HID + lane * 4]);
            acc_half4(acc, &g_h[v3 * HID + lane * 4]);
        }
        for (; k < rem; k++) {
            int v = __shfl_sync(0xffffffffu, vi, k);
            acc_half4(acc, &g_h[v * HID + lane * 4]);
        }
    }
    float sc = g_inv_ce[w];
    __half2 h01 = __floats2half2_rn(acc.x * sc, acc.y * sc);
    __half2 h23 = __floats2half2_rn(acc.z * sc, acc.w * sc);
    uint2 u;
    u.x = *(unsigned*)&h01;
    u.y = *(unsigned*)&h23;
    *(uint2*)&g_xe[w * HID + lane * 4] = u;
}

// ---------------- gather_ev core (gather + residual update) ----------------
__device__ __forceinline__ float4 ev_gather_update(int w, int lane) {
    int beg = g_off_v[w], end = g_off_v[w + 1];
    float4 acc = make_float4(0.f, 0.f, 0.f, 0.f);
    int j = beg;
    for (; j + 32 <= end; j += 32) {
        int ei = g_csr_ve[j + lane];
#pragma unroll
        for (int k = 0; k < 32; k += 4) {
            int e0 = __shfl_sync(0xffffffffu, ei, k);
            int e1 = __shfl_sync(0xffffffffu, ei, k + 1);
            int e2 = __shfl_sync(0xffffffffu, ei, k + 2);
            int e3 = __shfl_sync(0xffffffffu, ei, k + 3);
            acc_half4(acc, &g_xe[e0 * HID + lane * 4]);
            acc_half4(acc, &g_xe[e1 * HID + lane * 4]);
            acc_half4(acc, &g_xe[e2 * HID + lane * 4]);
            acc_half4(acc, &g_xe[e3 * HID + lane * 4]);
        }
    }
    int rem = end - j;
    if (rem > 0) {
        int ei = (lane < rem) ? g_csr_ve[j + lane] : 0;
        int k = 0;
        for (; k + 4 <= rem; k += 4) {
            int e0 = __shfl_sync(0xffffffffu, ei, k);
            int e1 = __shfl_sync(0xffffffffu, ei, k + 1);
            int e2 = __shfl_sync(0xffffffffu, ei, k + 2);
            int e3 = __shfl_sync(0xffffffffu, ei, k + 3);
            acc_half4(acc, &g_xe[e0 * HID + lane * 4]);
            acc_half4(acc, &g_xe[e1 * HID + lane * 4]);
            acc_half4(acc, &g_xe[e2 * HID + lane * 4]);
            acc_half4(acc, &g_xe[e3 * HID + lane * 4]);
        }
        for (; k < rem; k++) {
            int e = __shfl_sync(0xffffffffu, ei, k);
            acc_half4(acc, &g_xe[e * HID + lane * 4]);
        }
    }
    float s = g_inv_cv[w];
    float4 x = *(const float4*)&g_x[w * HID + lane * 4];
    x.x += fmaxf(acc.x * s, 0.0f);
    x.y += fmaxf(acc.y * s, 0.0f);
    x.z += fmaxf(acc.z * s, 0.0f);
    x.w += fmaxf(acc.w * s, 0.0f);
    *(float4*)&g_x[w * HID + lane * 4] = x;
    return x;
}

// ---------------- fused gather_ev + LN(next layer) -> g_a ------------------
__global__ void gather_ev_ln_kernel(const float* __restrict__ lng,
                                    const float* __restrict__ lnb) {
    int w = (blockIdx.x * blockDim.x + threadIdx.x) >> 5;
    int lane = threadIdx.x & 31;
    if (w >= NN) return;
    float4 xn = ev_gather_update(w, lane);

    float su = xn.x + xn.y + xn.z + xn.w;
    float sq = xn.x * xn.x + xn.y * xn.y + xn.z * xn.z + xn.w * xn.w;
#pragma unroll
    for (int off = 16; off > 0; off >>= 1) {
        su += __shfl_xor_sync(0xffffffffu, su, off);
        sq += __shfl_xor_sync(0xffffffffu, sq, off);
    }
    float mu  = su * (1.0f / 128.0f);
    float var = sq * (1.0f / 128.0f) - mu * mu;
    float rs  = rsqrtf(var + EPSV);
    float4 lg = *(const float4*)&lng[lane * 4];
    float4 lb = *(const float4*)&lnb[lane * 4];
    float h0 = fmaxf((xn.x - mu) * rs * lg.x + lb.x, 0.0f);
    float h1 = fmaxf((xn.y - mu) * rs * lg.y + lb.y, 0.0f);
    float h2 = fmaxf((xn.z - mu) * rs * lg.z + lb.z, 0.0f);
    float h3 = fmaxf((xn.w - mu) * rs * lg.w + lb.w, 0.0f);
    __half2 p01 = __floats2half2_rn(h0, h1);
    __half2 p23 = __floats2half2_rn(h2, h3);
    uint2 u;
    u.x = *(unsigned*)&p01;
    u.y = *(unsigned*)&p23;
    *(uint2*)&g_a[w * HID + lane * 4] = u;
}

// ---------------- plain gather_ev (last layer) ------------------------------
__global__ void gather_ev_kernel() {
    int w = (blockIdx.x * blockDim.x + threadIdx.x) >> 5;
    int lane = threadIdx.x & 31;
    if (w >= NN) return;
    ev_gather_update(w, lane);
}

// ---------------- head: log_softmax(x @ W_out + b_out) ---------------------
__global__ void out_kernel(const float* __restrict__ Wo,
                           const float* __restrict__ bo,
                           float* __restrict__ out) {
    __shared__ float WsT[NOUT][HID];
    __shared__ float bs[NOUT];
    int t = threadIdx.x;
    for (int i = t; i < HID * NOUT; i += 256) {
        int k = i >> 4, o = i & 15;
        WsT[o][k] = Wo[i];
    }
    if (t < NOUT) bs[t] = bo[t];
    __syncthreads();

    int w = (blockIdx.x * 256 + t) >> 5;
    int lane = t & 31;
    if (w >= NN) return;
    float4 x = *(const float4*)&g_x[w * HID + lane * 4];

    float r[NOUT];
#pragma unroll
    for (int o = 0; o < NOUT; o++) {
        float4 wv = *(const float4*)&WsT[o][lane * 4];
        float p = x.x * wv.x + x.y * wv.y + x.z * wv.z + x.w * wv.w;
#pragma unroll
        for (int off = 16; off > 0; off >>= 1)
            p += __shfl_xor_sync(0xffffffffu, p, off);
        r[o] = p + bs[o];
    }

    float m = r[0];
#pragma unroll
    for (int o = 1; o < NOUT; o++) m = fmaxf(m, r[o]);
    float sum = 0.0f;
#pragma unroll
    for (int o = 0; o < NOUT; o++) sum += expf(r[o] - m);
    float lse = m + logf(sum);

    if (lane == 0) {
#pragma unroll
        for (int o = 0; o < NOUT; o++)
            out[w * NOUT + o] = r[o] - lse;
    }
}

// ---------------- launcher ----------------
extern "C" void kernel_launch(void* const* d_in, const int* in_sizes, int n_in,
                              void* d_out, int out_size) {
    const float* X     = (const float*)d_in[0];
    const int*   v_idx = (const int*)  d_in[1];
    const int*   e_idx = (const int*)  d_in[2];
    const float* W_enc = (const float*)d_in[3];
    const float* b_enc = (const float*)d_in[4];
    const float* ln_g  = (const float*)d_in[5];
    const float* ln_b  = (const float*)d_in[6];
    const float* Wt    = (const float*)d_in[7];
    const float* bt    = (const float*)d_in[8];
    const float* W_out = (const float*)d_in[9];
    const float* b_out = (const float*)d_in[10];
    float* out = (float*)d_out;

    int* off_e; cudaGetSymbolAddress((void**)&off_e, g_off_e);
    int* off_v; cudaGetSymbolAddress((void**)&off_v, g_off_v);
    int* cnt_e; cudaGetSymbolAddress((void**)&cnt_e, g_cnt_e);
    int* cnt_v; cudaGetSymbolAddress((void**)&cnt_v, g_cnt_v);
    int* cur_e; cudaGetSymbolAddress((void**)&cur_e, g_cur_e);
    int* cur_v; cudaGetSymbolAddress((void**)&cur_v, g_cur_v);

    // zero the degree counters (graph-capturable async memset; no alloc)
    cudaMemsetAsync(cnt_e, 0, MM * sizeof(int));
    cudaMemsetAsync(cnt_v, 0, NN * sizeof(int));

    count_kernel<<<(PP + 255) / 256, 256>>>(v_idx, e_idx);
    inv_kernel<<<(NN + 255) / 256, 256>>>();

    {
        int nb = (MM + 1023) / 1024;
        scan_bsum_kernel<<<nb, 256>>>(cnt_e, MM);
        scan_part_kernel<<<1, 128>>>(nb);
        scan_final_kernel<<<nb, 256>>>(cnt_e, off_e, cur_e, MM);
    }
    {
        int nb = (NN + 1023) / 1024;
        scan_bsum_kernel<<<nb, 256>>>(cnt_v, NN);
        scan_part_kernel<<<1, 128>>>(nb);
        scan_final_kernel<<<nb, 256>>>(cnt_v, off_v, cur_v, NN);
    }
    fill_csr_kernel<<<(PP + 255) / 256, 256>>>(v_idx, e_idx);

    convert_w_kernel<<<(NLAYERS * HID * HID + 255) / 256, 256>>>(W_enc, Wt);

    enc_mma_kernel<<<(NN + 63) / 64, 256>>>(X, b_enc);

    const __half* wtT;
    { void* p; cudaGetSymbolAddress(&p, g_wtT); wtT = (const __half*)p; }

    // layer 0 (LN from g_x)
    ln_mma_kernel<<<(NN + 63) / 64, 256>>>(ln_g, ln_b, wtT, bt);

    for (int l = 0; l < NLAYERS - 1; l++) {
        gather_ve_kernel<<<(MM + 7) / 8, 256>>>();
        gather_ev_ln_kernel<<<(NN + 7) / 8, 256>>>(ln_g + (l + 1) * HID,
                                                   ln_b + (l + 1) * HID);
        a_mma_kernel<<<(NN + 63) / 64, 256>>>(wtT + (l + 1) * HID * HID,
                                              bt + (l + 1) * HID);
    }
    gather_ve_kernel<<<(MM + 7) / 8, 256>>>();
    gather_ev_kernel<<<(NN + 7) / 8, 256>>>();

    out_kernel<<<NN / 8, 256>>>(W_out, b_out, out);
}

// round 17
// speedup vs baseline: 1.0544x; 1.0022x over previous
#include <cuda_runtime.h>
#include <cuda_fp16.h>
#include <stdint.h>

#define NN 100000
#define MM 20000
#define PP 1600000
#define CIN 768
#define HID 128
#define NLAYERS 16
#define NOUT 16
#define EPSV 1e-5f

#define NB_E 20            // (MM + 1023) / 1024
#define NB_V 98            // (NN + 1023) / 1024
#define NB_TOT (NB_E + NB_V)

// ---------------- scratch ----------------
__device__ float  g_x[NN * HID];        // residual stream fp32
__device__ __half g_a[NN * HID];        // LN+relu'd activations fp16 (MMA input)
__device__ __half g_h[NN * HID];        // post-theta fp16
__device__ __half g_xe[MM * HID];       // edge features fp16
__device__ __half g_weT[HID * CIN];     // W_enc^T  [n][k]
__device__ __half g_wtT[NLAYERS * HID * HID]; // Wt^T per layer [n][k]
__device__ float  g_inv_ce[MM];
__device__ float  g_inv_cv[NN];
__device__ int    g_cnt_e[MM];
__device__ int    g_cnt_v[NN];
__device__ int    g_off_e[MM + 1];
__device__ int    g_off_v[NN + 1];
__device__ int    g_cur_e[MM];
__device__ int    g_cur_v[NN];
__device__ int    g_csr_ev[PP];
__device__ int    g_csr_ve[PP];
__device__ int    g_part[128];

// ---------------- degree counting ----------------
__global__ void count_kernel(const int* __restrict__ v_idx,
                             const int* __restrict__ e_idx) {
    int i = blockIdx.x * blockDim.x + threadIdx.x;
    if (i < PP) {
        atomicAdd(&g_cnt_e[e_idx[i]], 1);
        atomicAdd(&g_cnt_v[v_idx[i]], 1);
    }
}

__global__ void inv_kernel() {
    int i = blockIdx.x * blockDim.x + threadIdx.x;
    if (i < MM) g_inv_ce[i] = 1.0f / fmaxf((float)g_cnt_e[i], 1.0f);
    if (i < NN) g_inv_cv[i] = 1.0f / fmaxf((float)g_cnt_v[i], 1.0f);
}

// ---------------- fused 2-level scan over BOTH count arrays -----------------
// block b < NB_E handles edge chunk b; block b >= NB_E handles vertex chunk.
__global__ void scan_bsum2_kernel() {
    __shared__ int wsum[8];
    int t = threadIdx.x;
    int b = blockIdx.x;
    const int* cnt;
    int n, base;
    if (b < NB_E) { cnt = g_cnt_e; n = MM; base = b * 1024; }
    else          { cnt = g_cnt_v; n = NN; base = (b - NB_E) * 1024; }
    int s = 0;
    for (int i = t; i < 1024; i += 256) {
        int idx = base + i;
        if (idx < n) s += cnt[idx];
    }
    int lane = t & 31, wid = t >> 5;
#pragma unroll
    for (int d = 16; d > 0; d >>= 1) s += __shfl_xor_sync(0xffffffffu, s, d);
    if (lane == 0) wsum[wid] = s;
    __syncthreads();
    if (t == 0) {
        int tot = 0;
#pragma unroll
        for (int i = 0; i < 8; i++) tot += wsum[i];
        g_part[b] = tot;
    }
}

// exclusive scan of partials, per segment (edges [0,NB_E), vertices [NB_E,NB_TOT))
__global__ void scan_part2_kernel() {
    __shared__ int sm[128];
    int t = threadIdx.x;
    sm[t] = (t < NB_TOT) ? g_part[t] : 0;
    __syncthreads();
    if (t == 0) {
        int run = 0;
        for (int i = 0; i < NB_E; i++) {
            int v = sm[i];
            sm[i] = run;
            run += v;
        }
        run = 0;
        for (int i = NB_E; i < NB_TOT; i++) {
            int v = sm[i];
            sm[i] = run;
            run += v;
        }
    }
    __syncthreads();
    if (t < NB_TOT) g_part[t] = sm[t];
}

__global__ void scan_final2_kernel() {
    __shared__ int wpre[8];
    int t = threadIdx.x;
    int lane = t & 31, wid = t >> 5;
    int b = blockIdx.x;
    const int* cnt;
    int* off;
    int* cur;
    int n, cbase;
    if (b < NB_E) {
        cnt = g_cnt_e; off = g_off_e; cur = g_cur_e; n = MM;
        cbase = b * 1024;
    } else {
        cnt = g_cnt_v; off = g_off_v; cur = g_cur_v; n = NN;
        cbase = (b - NB_E) * 1024;
    }
    int base = cbase + t * 4;

    int local[4];
    int s = 0;
#pragma unroll
    for (int j = 0; j < 4; j++) {
        int idx = base + j;
        int v = (idx < n) ? cnt[idx] : 0;
        if (idx < n) cur[idx] = 0;
        local[j] = v;
        s += v;
    }
    int incl = s;
#pragma unroll
    for (int d = 1; d < 32; d <<= 1) {
        int y = __shfl_up_sync(0xffffffffu, incl, d);
        if (lane >= d) incl += y;
    }
    if (lane == 31) wpre[wid] = incl;
    __syncthreads();
    if (t == 0) {
        int run = 0;
#pragma unroll
        for (int i = 0; i < 8; i++) {
            int v = wpre[i];
            wpre[i] = run;
            run += v;
        }
    }
    __syncthreads();
    int excl = incl - s + wpre[wid] + g_part[b];
    int run = excl;
#pragma unroll
    for (int j = 0; j < 4; j++) {
        int idx = base + j;
        run += local[j];
        if (idx < n) off[idx + 1] = run;
    }
    if (cbase == 0 && t == 0) off[0] = 0;
}

// ---------------- CSR fill --------------------------------------------------
__global__ void fill_csr_kernel(const int* __restrict__ v_idx,
                                const int* __restrict__ e_idx) {
    int i = blockIdx.x * blockDim.x + threadIdx.x;
    if (i >= PP) return;
    int v = v_idx[i];
    int e = e_idx[i];
    int pe = atomicAdd(&g_cur_e[e], 1);
    g_csr_ev[g_off_e[e] + pe] = v;
    int pv = atomicAdd(&g_cur_v[v], 1);
    g_csr_ve[g_off_v[v] + pv] = e;
}

// ---------------- weight conversion ----------------
__global__ void convert_w_kernel(const float* __restrict__ We,
                                 const float* __restrict__ Wt) {
    int i = blockIdx.x * blockDim.x + threadIdx.x;
    if (i < CIN * HID) {
        int k = i / HID, n = i % HID;
        g_weT[n * CIN + k] = __float2half(We[i]);
    }
    if (i < NLAYERS * HID * HID) {
        int l = i >> 14;
        int r = i & 16383;
        int k = r >> 7, n = r & 127;
        g_wtT[(l << 14) + n * HID + k] = __float2half(Wt[i]);
    }
}

// ---------------- mma helper ----------------
__device__ __forceinline__ void mma16816(float* c, uint32_t a0, uint32_t a1,
                                         uint32_t a2, uint32_t a3,
                                         uint32_t b0, uint32_t b1) {
    asm volatile(
        "mma.sync.aligned.m16n8k16.row.col.f32.f16.f16.f32 "
        "{%0,%1,%2,%3},{%4,%5,%6,%7},{%8,%9},{%0,%1,%2,%3};"
        : "+f"(c[0]), "+f"(c[1]), "+f"(c[2]), "+f"(c[3])
        : "r"(a0), "r"(a1), "r"(a2), "r"(a3), "r"(b0), "r"(b1));
}

__device__ __forceinline__ uint4 pack_half8(const float* f) {
    __half2 h0 = __floats2half2_rn(f[0], f[1]);
    __half2 h1 = __floats2half2_rn(f[2], f[3]);
    __half2 h2 = __floats2half2_rn(f[4], f[5]);
    __half2 h3 = __floats2half2_rn(f[6], f[7]);
    uint4 u;
    u.x = *(unsigned*)&h0; u.y = *(unsigned*)&h1;
    u.z = *(unsigned*)&h2; u.w = *(unsigned*)&h3;
    return u;
}

// ---------------- encoder GEMM (tensor core) --------------------------------
__global__ void enc_mma_kernel(const float* __restrict__ X,
                               const float* __restrict__ bias) {
    __shared__ __half As[2][64][24];
    __shared__ __half Bs[2][128][24];
    int t = threadIdx.x;
    int lane = t & 31, wid = t >> 5;
    int wr = wid >> 1, wc = wid & 1;
    int row0 = blockIdx.x * 64;

    float acc[8][4];
#pragma unroll
    for (int j = 0; j < 8; j++)
#pragma unroll
        for (int q = 0; q < 4; q++) acc[j][q] = 0.0f;

    {
        int kk = (t & 1) * 8;
        if (t < 128) {
            int row = t >> 1;
            int gr = row0 + row;
            float f[8] = {0, 0, 0, 0, 0, 0, 0, 0};
            if (gr < NN) {
                float4 v0 = *(const float4*)&X[gr * CIN + kk];
                float4 v1 = *(const float4*)&X[gr * CIN + kk + 4];
                f[0] = v0.x; f[1] = v0.y; f[2] = v0.z; f[3] = v0.w;
                f[4] = v1.x; f[5] = v1.y; f[6] = v1.z; f[7] = v1.w;
            }
            *(uint4*)&As[0][row][kk] = pack_half8(f);
        }
        int n = t >> 1;
        *(uint4*)&Bs[0][n][kk] = *(const uint4*)&g_weT[n * CIN + kk];
    }
    __syncthreads();

    for (int c = 0; c < CIN / 16; c++) {
        int cur = c & 1, nxt = cur ^ 1;
        if (c + 1 < CIN / 16) {
            int k0 = (c + 1) * 16;
            int kk = (t & 1) * 8;
            if (t < 128) {
                int row = t >> 1;
                int gr = row0 + row;
                float f[8] = {0, 0, 0, 0, 0, 0, 0, 0};
                if (gr < NN) {
                    float4 v0 = *(const float4*)&X[gr * CIN + k0 + kk];
                    float4 v1 = *(const float4*)&X[gr * CIN + k0 + kk + 4];
                    f[0] = v0.x; f[1] = v0.y; f[2] = v0.z; f[3] = v0.w;
                    f[4] = v1.x; f[5] = v1.y; f[6] = v1.z; f[7] = v1.w;
                }
                *(uint4*)&As[nxt][row][kk] = pack_half8(f);
            }
            int n = t >> 1;
            *(uint4*)&Bs[nxt][n][kk] = *(const uint4*)&g_weT[n * CIN + k0 + kk];
        }
        int ar = wr * 16 + (lane >> 2);
        int cx = (lane & 3) * 2;
        uint32_t a0 = *(uint32_t*)&As[cur][ar][cx];
        uint32_t a1 = *(uint32_t*)&As[cur][ar + 8][cx];
        uint32_t a2 = *(uint32_t*)&As[cur][ar][cx + 8];
        uint32_t a3 = *(uint32_t*)&As[cur][ar + 8][cx + 8];
#pragma unroll
        for (int j = 0; j < 8; j++) {
            int n = wc * 64 + j * 8 + (lane >> 2);
            uint32_t b0 = *(uint32_t*)&Bs[cur][n][cx];
            uint32_t b1 = *(uint32_t*)&Bs[cur][n][cx + 8];
            mma16816(acc[j], a0, a1, a2, a3, b0, b1);
        }
        __syncthreads();
    }

    int r1 = row0 + wr * 16 + (lane >> 2);
    int r2 = r1 + 8;
#pragma unroll
    for (int j = 0; j < 8; j++) {
        int cb = wc * 64 + j * 8 + (lane & 3) * 2;
        float b0 = bias[cb], b1 = bias[cb + 1];
        if (r1 < NN)
            *(float2*)&g_x[r1 * HID + cb] = make_float2(acc[j][0] + b0, acc[j][1] + b1);
        if (r2 < NN)
            *(float2*)&g_x[r2 * HID + cb] = make_float2(acc[j][2] + b0, acc[j][3] + b1);
    }
}

// ---------------- theta MMA tail (shared) -----------------------------------
__device__ __forceinline__ void theta_mma_tail(
    __half (*As)[136], __half (*Ws)[72],
    const __half* __restrict__ WtT, const float* __restrict__ bb,
    int row0, int t, int lane, int wid) {
    int wr = wid >> 1, wc = wid & 1;

    float acc[8][4];
#pragma unroll
    for (int j = 0; j < 8; j++)
#pragma unroll
        for (int q = 0; q < 4; q++) acc[j][q] = 0.0f;

#pragma unroll
    for (int s = 0; s < 2; s++) {
#pragma unroll
        for (int i = 0; i < 4; i++) {
            int idx = t + i * 256;
            int n = idx >> 3, k = (idx & 7) * 8;
            *(uint4*)&Ws[n][k] = *(const uint4*)&WtT[n * HID + s * 64 + k];
        }
        __syncthreads();
#pragma unroll
        for (int c = 0; c < 4; c++) {
            int ka = s * 64 + c * 16;
            int kw = c * 16;
            int ar = wr * 16 + (lane >> 2);
            int q2 = (lane & 3) * 2;
            uint32_t a0 = *(uint32_t*)&As[ar][ka + q2];
            uint32_t a1 = *(uint32_t*)&As[ar + 8][ka + q2];
            uint32_t a2 = *(uint32_t*)&As[ar][ka + q2 + 8];
            uint32_t a3 = *(uint32_t*)&As[ar + 8][ka + q2 + 8];
#pragma unroll
            for (int j = 0; j < 8; j++) {
                int n = wc * 64 + j * 8 + (lane >> 2);
                uint32_t b0 = *(uint32_t*)&Ws[n][kw + q2];
                uint32_t b1 = *(uint32_t*)&Ws[n][kw + q2 + 8];
                mma16816(acc[j], a0, a1, a2, a3, b0, b1);
            }
        }
        __syncthreads();
    }

    int r1 = row0 + wr * 16 + (lane >> 2);
    int r2 = r1 + 8;
#pragma unroll
    for (int j = 0; j < 8; j++) {
        int cb = wc * 64 + j * 8 + (lane & 3) * 2;
        float b0 = bb[cb], b1 = bb[cb + 1];
        if (r1 < NN) {
            __half2 h = __floats2half2_rn(acc[j][0] + b0, acc[j][1] + b1);
            *(unsigned*)&g_h[r1 * HID + cb] = *(unsigned*)&h;
        }
        if (r2 < NN) {
            __half2 h = __floats2half2_rn(acc[j][2] + b0, acc[j][3] + b1);
            *(unsigned*)&g_h[r2 * HID + cb] = *(unsigned*)&h;
        }
    }
}

// ---------------- layer 0: LN(x) + theta (reads g_x fp32) ------------------
__global__ void ln_mma_kernel(const float* __restrict__ lng,
                              const float* __restrict__ lnb,
                              const __half* __restrict__ WtT,
                              const float* __restrict__ bb) {
    __shared__ __half As[64][136];
    __shared__ __half Ws[128][72];
    int t = threadIdx.x;
    int lane = t & 31, wid = t >> 5;
    int row0 = blockIdx.x * 64;

    float4 lg = *(const float4*)&lng[lane * 4];
    float4 lb = *(const float4*)&lnb[lane * 4];
#pragma unroll
    for (int rr = 0; rr < 8; rr++) {
        int r = wid * 8 + rr;
        int row = row0 + r;
        float4 v = make_float4(0.f, 0.f, 0.f, 0.f);
        if (row < NN) v = *(const float4*)&g_x[row * HID + lane * 4];
        float s  = v.x + v.y + v.z + v.w;
        float sq = v.x * v.x + v.y * v.y + v.z * v.z + v.w * v.w;
#pragma unroll
        for (int off = 16; off > 0; off >>= 1) {
            s  += __shfl_xor_sync(0xffffffffu, s, off);
            sq += __shfl_xor_sync(0xffffffffu, sq, off);
        }
        float mu  = s * (1.0f / 128.0f);
        float var = sq * (1.0f / 128.0f) - mu * mu;
        float rs  = rsqrtf(var + EPSV);
        float h0 = fmaxf((v.x - mu) * rs * lg.x + lb.x, 0.0f);
        float h1 = fmaxf((v.y - mu) * rs * lg.y + lb.y, 0.0f);
        float h2 = fmaxf((v.z - mu) * rs * lg.z + lb.z, 0.0f);
        float h3 = fmaxf((v.w - mu) * rs * lg.w + lb.w, 0.0f);
        __half2 p01 = __floats2half2_rn(h0, h1);
        __half2 p23 = __floats2half2_rn(h2, h3);
        uint2 u;
        u.x = *(unsigned*)&p01;
        u.y = *(unsigned*)&p23;
        *(uint2*)&As[r][lane * 4] = u;
    }
    __syncthreads();
    theta_mma_tail(As, Ws, WtT, bb, row0, t, lane, wid);
}

// ---------------- layers >=1: theta on precomputed g_a ----------------------
__global__ void a_mma_kernel(const __half* __restrict__ WtT,
                             const float* __restrict__ bb) {
    __shared__ __half As[64][136];
    __shared__ __half Ws[128][72];
    int t = threadIdx.x;
    int lane = t & 31, wid = t >> 5;
    int row0 = blockIdx.x * 64;

#pragma unroll
    for (int i = 0; i < 4; i++) {
        int idx = t + i * 256;
        int row = idx >> 4;
        int cg  = idx & 15;
        int grow = row0 + row;
        uint4 u = make_uint4(0, 0, 0, 0);
        if (grow < NN) u = *(const uint4*)&g_a[grow * HID + cg * 8];
        *(uint4*)&As[row][cg * 8] = u;
    }
    __syncthreads();
    theta_mma_tail(As, Ws, WtT, bb, row0, t, lane, wid);
}

// helper: load 4 halves (8B) and add into float4 accumulator
__device__ __forceinline__ void acc_half4(float4& acc, const __half* p) {
    uint2 u = *(const uint2*)p;
    __half2 a = *(__half2*)&u.x;
    __half2 b = *(__half2*)&u.y;
    float2 fa = __half22float2(a);
    float2 fb = __half22float2(b);
    acc.x += fa.x; acc.y += fa.y; acc.z += fb.x; acc.w += fb.y;
}

// ---------------- pass 1: Xe[e] = (sum_{v in e} h[v]) * inv_ce[e] ----------
__global__ void gather_ve_kernel() {
    int w = (blockIdx.x * blockDim.x + threadIdx.x) >> 5;
    int lane = threadIdx.x & 31;
    if (w >= MM) return;
    int beg = g_off_e[w], end = g_off_e[w + 1];

    float4 acc = make_float4(0.f, 0.f, 0.f, 0.f);
    int j = beg;
    for (; j + 32 <= end; j += 32) {
        int vi = g_csr_ev[j + lane];
#pragma unroll
        for (int k = 0; k < 32; k += 4) {
            int v0 = __shfl_sync(0xffffffffu, vi, k);
            int v1 = __shfl_sync(0xffffffffu, vi, k + 1);
            int v2 = __shfl_sync(0xffffffffu, vi, k + 2);
            int v3 = __shfl_sync(0xffffffffu, vi, k + 3);
            acc_half4(acc, &g_h[v0 * HID + lane * 4]);
            acc_half4(acc, &g_h[v1 * HID + lane * 4]);
            acc_half4(acc, &g_h[v2 * HID + lane * 4]);
            acc_half4(acc, &g_h[v3 * HID + lane * 4]);
        }
    }
    int rem = end - j;
    if (rem > 0) {
        int vi = (lane < rem) ? g_csr_ev[j + lane] : 0;
        int k = 0;
        for (; k + 4 <= rem; k += 4) {
            int v0 = __shfl_sync(0xffffffffu, vi, k);
            int v1 = __shfl_sync(0xffffffffu, vi, k + 1);
            int v2 = __shfl_sync(0xffffffffu, vi, k + 2);
            int v3 = __shfl_sync(0xffffffffu, vi, k + 3);
            acc_half4(acc, &g_h[v0 * HID + lane * 4]);
            acc_half4(acc, &g_h[v1 * HID + lane * 4]);
            acc_half4(acc, &g_h[v2 * HID + lane * 4]);
            acc_half4(acc, &g_h[v3 * HID + lane * 4]);
        }
        for (; k < rem; k++) {
            int v = __shfl_sync(0xffffffffu, vi, k);
            acc_half4(acc, &g_h[v * HID + lane * 4]);
        }
    }
    float sc = g_inv_ce[w];
    __half2 h01 = __floats2half2_rn(acc.x * sc, acc.y * sc);
    __half2 h23 = __floats2half2_rn(acc.z * sc, acc.w * sc);
    uint2 u;
    u.x = *(unsigned*)&h01;
    u.y = *(unsigned*)&h23;
    *(uint2*)&g_xe[w * HID + lane * 4] = u;
}

// ---------------- gather_ev core (gather + residual update) ----------------
__device__ __forceinline__ float4 ev_gather_update(int w, int lane) {
    int beg = g_off_v[w], end = g_off_v[w + 1];
    float4 acc = make_float4(0.f, 0.f, 0.f, 0.f);
    int j = beg;
    for (; j + 32 <= end; j += 32) {
        int ei = g_csr_ve[j + lane];
#pragma unroll
        for (int k = 0; k < 32; k += 4) {
            int e0 = __shfl_sync(0xffffffffu, ei, k);
            int e1 = __shfl_sync(0xffffffffu, ei, k + 1);
            int e2 = __shfl_sync(0xffffffffu, ei, k + 2);
            int e3 = __shfl_sync(0xffffffffu, ei, k + 3);
            acc_half4(acc, &g_xe[e0 * HID + lane * 4]);
            acc_half4(acc, &g_xe[e1 * HID + lane * 4]);
            acc_half4(acc, &g_xe[e2 * HID + lane * 4]);
            acc_half4(acc, &g_xe[e3 * HID + lane * 4]);
        }
    }
    int rem = end - j;
    if (rem > 0) {
        int ei = (lane < rem) ? g_csr_ve[j + lane] : 0;
        int k = 0;
        for (; k + 4 <= rem; k += 4) {
            int e0 = __shfl_sync(0xffffffffu, ei, k);
            int e1 = __shfl_sync(0xffffffffu, ei, k + 1);
            int e2 = __shfl_sync(0xffffffffu, ei, k + 2);
            int e3 = __shfl_sync(0xffffffffu, ei, k + 3);
            acc_half4(acc, &g_xe[e0 * HID + lane * 4]);
            acc_half4(acc, &g_xe[e1 * HID + lane * 4]);
            acc_half4(acc, &g_xe[e2 * HID + lane * 4]);
            acc_half4(acc, &g_xe[e3 * HID + lane * 4]);
        }
        for (; k < rem; k++) {
            int e = __shfl_sync(0xffffffffu, ei, k);
            acc_half4(acc, &g_xe[e * HID + lane * 4]);
        }
    }
    float s = g_inv_cv[w];
    float4 x = *(const float4*)&g_x[w * HID + lane * 4];
    x.x += fmaxf(acc.x * s, 0.0f);
    x.y += fmaxf(acc.y * s, 0.0f);
    x.z += fmaxf(acc.z * s, 0.0f);
    x.w += fmaxf(acc.w * s, 0.0f);
    *(float4*)&g_x[w * HID + lane * 4] = x;
    return x;
}

// ---------------- fused gather_ev + LN(next layer) -> g_a ------------------
__global__ void gather_ev_ln_kernel(const float* __restrict__ lng,
                                    const float* __restrict__ lnb) {
    int w = (blockIdx.x * blockDim.x + threadIdx.x) >> 5;
    int lane = threadIdx.x & 31;
    if (w >= NN) return;
    float4 xn = ev_gather_update(w, lane);

    float su = xn.x + xn.y + xn.z + xn.w;
    float sq = xn.x * xn.x + xn.y * xn.y + xn.z * xn.z + xn.w * xn.w;
#pragma unroll
    for (int off = 16; off > 0; off >>= 1) {
        su += __shfl_xor_sync(0xffffffffu, su, off);
        sq += __shfl_xor_sync(0xffffffffu, sq, off);
    }
    float mu  = su * (1.0f / 128.0f);
    float var = sq * (1.0f / 128.0f) - mu * mu;
    float rs  = rsqrtf(var + EPSV);
    float4 lg = *(const float4*)&lng[lane * 4];
    float4 lb = *(const float4*)&lnb[lane * 4];
    float h0 = fmaxf((xn.x - mu) * rs * lg.x + lb.x, 0.0f);
    float h1 = fmaxf((xn.y - mu) * rs * lg.y + lb.y, 0.0f);
    float h2 = fmaxf((xn.z - mu) * rs * lg.z + lb.z, 0.0f);
    float h3 = fmaxf((xn.w - mu) * rs * lg.w + lb.w, 0.0f);
    __half2 p01 = __floats2half2_rn(h0, h1);
    __half2 p23 = __floats2half2_rn(h2, h3);
    uint2 u;
    u.x = *(unsigned*)&p01;
    u.y = *(unsigned*)&p23;
    *(uint2*)&g_a[w * HID + lane * 4] = u;
}

// ---------------- plain gather_ev (last layer) ------------------------------
__global__ void gather_ev_kernel() {
    int w = (blockIdx.x * blockDim.x + threadIdx.x) >> 5;
    int lane = threadIdx.x & 31;
    if (w >= NN) return;
    ev_gather_update(w, lane);
}

// ---------------- head: log_softmax(x @ W_out + b_out) ---------------------
__global__ void out_kernel(const float* __restrict__ Wo,
                           const float* __restrict__ bo,
                           float* __restrict__ out) {
    __shared__ float WsT[NOUT][HID];
    __shared__ float bs[NOUT];
    int t = threadIdx.x;
    for (int i = t; i < HID * NOUT; i += 256) {
        int k = i >> 4, o = i & 15;
        WsT[o][k] = Wo[i];
    }
    if (t < NOUT) bs[t] = bo[t];
    __syncthreads();

    int w = (blockIdx.x * 256 + t) >> 5;
    int lane = t & 31;
    if (w >= NN) return;
    float4 x = *(const float4*)&g_x[w * HID + lane * 4];

    float r[NOUT];
#pragma unroll
    for (int o = 0; o < NOUT; o++) {
        float4 wv = *(const float4*)&WsT[o][lane * 4];
        float p = x.x * wv.x + x.y * wv.y + x.z * wv.z + x.w * wv.w;
#pragma unroll
        for (int off = 16; off > 0; off >>= 1)
            p += __shfl_xor_sync(0xffffffffu, p, off);
        r[o] = p + bs[o];
    }

    float m = r[0];
#pragma unroll
    for (int o = 1; o < NOUT; o++) m = fmaxf(m, r[o]);
    float sum = 0.0f;
#pragma unroll
    for (int o = 0; o < NOUT; o++) sum += expf(r[o] - m);
    float lse = m + logf(sum);

    if (lane == 0) {
#pragma unroll
        for (int o = 0; o < NOUT; o++)
            out[w * NOUT + o] = r[o] - lse;
    }
}

// ---------------- launcher ----------------
extern "C" void kernel_launch(void* const* d_in, const int* in_sizes, int n_in,
                              void* d_out, int out_size) {
    const float* X     = (const float*)d_in[0];
    const int*   v_idx = (const int*)  d_in[1];
    const int*   e_idx = (const int*)  d_in[2];
    const float* W_enc = (const float*)d_in[3];
    const float* b_enc = (const float*)d_in[4];
    const float* ln_g  = (const float*)d_in[5];
    const float* ln_b  = (const float*)d_in[6];
    const float* Wt    = (const float*)d_in[7];
    const float* bt    = (const float*)d_in[8];
    const float* W_out = (const float*)d_in[9];
    const float* b_out = (const float*)d_in[10];
    float* out = (float*)d_out;

    int* cnt_e; cudaGetSymbolAddress((void**)&cnt_e, g_cnt_e);
    int* cnt_v; cudaGetSymbolAddress((void**)&cnt_v, g_cnt_v);

    // zero the degree counters (graph-capturable async memset; no alloc)
    cudaMemsetAsync(cnt_e, 0, MM * sizeof(int));
    cudaMemsetAsync(cnt_v, 0, NN * sizeof(int));

    count_kernel<<<(PP + 255) / 256, 256>>>(v_idx, e_idx);
    inv_kernel<<<(NN + 255) / 256, 256>>>();

    // fused 2-level scans for both CSRs (3 launches total)
    scan_bsum2_kernel<<<NB_TOT, 256>>>();
    scan_part2_kernel<<<1, 128>>>();
    scan_final2_kernel<<<NB_TOT, 256>>>();

    fill_csr_kernel<<<(PP + 255) / 256, 256>>>(v_idx, e_idx);

    convert_w_kernel<<<(NLAYERS * HID * HID + 255) / 256, 256>>>(W_enc, Wt);

    enc_mma_kernel<<<(NN + 63) / 64, 256>>>(X, b_enc);

    const __half* wtT;
    { void* p; cudaGetSymbolAddress(&p, g_wtT); wtT = (const __half*)p; }

    // layer 0 (LN from g_x)
    ln_mma_kernel<<<(NN + 63) / 64, 256>>>(ln_g, ln_b, wtT, bt);

    for (int l = 0; l < NLAYERS - 1; l++) {
        gather_ve_kernel<<<(MM + 7) / 8, 256>>>();
        gather_ev_ln_kernel<<<(NN + 7) / 8, 256>>>(ln_g + (l + 1) * HID,
                                                   ln_b + (l + 1) * HID);
        a_mma_kernel<<<(NN + 63) / 64, 256>>>(wtT + (l + 1) * HID * HID,
                                              bt + (l + 1) * HID);
    }
    gather_ve_kernel<<<(MM + 7) / 8, 256>>>();
    gather_ev_kernel<<<(NN + 7) / 8, 256>>>();

    out_kernel<<<NN / 8, 256>>>(W_out, b_out, out);
}